// round 3
// baseline (speedup 1.0000x reference)
#include <cuda_runtime.h>

#define NN 100000
#define NE 1600000
#define HID 128
#define INF_ 7
#define NG 512
#define SCAN_BLK ((NN + 1023) / 1024)

// ---------------- scratch (device globals: no allocation allowed) ----------
__device__ int   g_indeg[NN];
__device__ int   g_cursor[NN];
__device__ int   g_rowstart[NN];
__device__ float g_dis[NN];
__device__ int   g_csr_src[NE];
__device__ float g_csr_w[NE];
__device__ int   g_bsums[SCAN_BLK];
__device__ float g_h1[(size_t)NN * HID];
__device__ float g_h2[(size_t)NN * HID];
__device__ float g_agg[(size_t)NN * HID];
__device__ float g_pool[NG * HID];

// ---------------- graph preprocessing --------------------------------------
__global__ void k_init() {
    int i = blockIdx.x * blockDim.x + threadIdx.x;
    if (i < NN) { g_indeg[i] = 0; g_cursor[i] = 0; }
    if (i < NG * HID) g_pool[i] = 0.0f;
}

__global__ void k_hist(const int* __restrict__ dst) {
    int e = blockIdx.x * blockDim.x + threadIdx.x;
    if (e < NE) atomicAdd(&g_indeg[dst[e]], 1);
}

__global__ void k_dis() {
    int i = blockIdx.x * blockDim.x + threadIdx.x;
    if (i < NN) g_dis[i] = rsqrtf((float)(g_indeg[i] + 1));  // +1 self loop
}

__global__ void k_scan1() {
    __shared__ int s[1024];
    int tid = threadIdx.x;
    int i = blockIdx.x * 1024 + tid;
    int v = (i < NN) ? g_indeg[i] : 0;
    s[tid] = v;
    __syncthreads();
    for (int off = 1; off < 1024; off <<= 1) {
        int t = (tid >= off) ? s[tid - off] : 0;
        __syncthreads();
        s[tid] += t;
        __syncthreads();
    }
    if (i < NN) g_rowstart[i] = s[tid] - v;  // exclusive
    if (tid == 1023) g_bsums[blockIdx.x] = s[1023];
}

__global__ void k_scan2() {
    if (threadIdx.x == 0) {
        int acc = 0;
        for (int b = 0; b < SCAN_BLK; ++b) {
            int v = g_bsums[b];
            g_bsums[b] = acc;
            acc += v;
        }
    }
}

__global__ void k_scan3() {
    int i = blockIdx.x * 1024 + threadIdx.x;
    if (i < NN) g_rowstart[i] += g_bsums[blockIdx.x];
}

__global__ void k_scatter(const int* __restrict__ src, const int* __restrict__ dst) {
    int e = blockIdx.x * blockDim.x + threadIdx.x;
    if (e >= NE) return;
    int s = src[e], d = dst[e];
    int pos = atomicAdd(&g_cursor[d], 1);
    int idx = g_rowstart[d] + pos;
    g_csr_src[idx] = s;
    g_csr_w[idx] = g_dis[s] * g_dis[d];
}

// ---------------- layer 1: aggregate x (7 feats) fused with 7x128 GEMM -----
__global__ void k_layer1(const float* __restrict__ x, const float* __restrict__ W1,
                         const float* __restrict__ b1) {
    __shared__ float sW[INF_ * HID];
    __shared__ float sb[HID];
    int tid = threadIdx.x;
    for (int j = tid; j < INF_ * HID; j += blockDim.x) sW[j] = W1[j];
    if (tid < HID) sb[tid] = b1[tid];
    __syncthreads();

    int wid = tid >> 5, lane = tid & 31;
    int i = blockIdx.x * 8 + wid;
    if (i >= NN) return;

    int start = g_rowstart[i], len = g_indeg[i];
    float acc[INF_];
#pragma unroll
    for (int k = 0; k < INF_; k++) acc[k] = 0.0f;

    for (int e = start + lane; e < start + len; e += 32) {
        int s = g_csr_src[e];
        float w = g_csr_w[e];
        const float* xs = x + (size_t)s * INF_;
#pragma unroll
        for (int k = 0; k < INF_; k++) acc[k] += w * xs[k];
    }
#pragma unroll
    for (int k = 0; k < INF_; k++) {
#pragma unroll
        for (int off = 16; off > 0; off >>= 1)
            acc[k] += __shfl_xor_sync(0xffffffffu, acc[k], off);
    }
    float d = g_dis[i];
    float sw = d * d;
    const float* xi = x + (size_t)i * INF_;
#pragma unroll
    for (int k = 0; k < INF_; k++) acc[k] += sw * xi[k];

    int j0 = lane * 4;
    float ov[4];
#pragma unroll
    for (int j = 0; j < 4; j++) {
        float v = sb[j0 + j];
#pragma unroll
        for (int k = 0; k < INF_; k++) v += acc[k] * sW[k * HID + j0 + j];
        ov[j] = fmaxf(v, 0.0f);
    }
    *(float4*)&g_h1[(size_t)i * HID + j0] = make_float4(ov[0], ov[1], ov[2], ov[3]);
}

// ---------------- 128-feature CSR gather-aggregate -------------------------
__global__ void k_agg128(int src_sel) {
    const float* __restrict__ h = (src_sel == 0) ? g_h1 : g_h2;
    int wid = threadIdx.x >> 5, lane = threadIdx.x & 31;
    int i = blockIdx.x * 8 + wid;
    if (i >= NN) return;
    int start = g_rowstart[i], len = g_indeg[i];
    float d = g_dis[i];
    float sw = d * d;
    float4 acc = *(const float4*)&h[(size_t)i * HID + lane * 4];
    acc.x *= sw; acc.y *= sw; acc.z *= sw; acc.w *= sw;
    int end = start + len;
#pragma unroll 4
    for (int e = start; e < end; ++e) {
        int s = g_csr_src[e];
        float w = g_csr_w[e];
        float4 v = *(const float4*)&h[(size_t)s * HID + lane * 4];
        acc.x += w * v.x; acc.y += w * v.y; acc.z += w * v.z; acc.w += w * v.w;
    }
    *(float4*)&g_agg[(size_t)i * HID + lane * 4] = acc;
}

// ---------------- fp32 GEMM: C = relu(g_agg @ W + b), 64x64 tiles ----------
__global__ void k_gemm(int out_sel, const float* __restrict__ W,
                       const float* __restrict__ b) {
    float* __restrict__ C = (out_sel == 0) ? g_h2 : g_h1;
    const float* __restrict__ A = g_agg;
    __shared__ __align__(16) float As[16][68];
    __shared__ __align__(16) float Bs[16][64];
    int tid = threadIdx.x;
    int tx = tid & 15, ty = tid >> 4;
    int m0 = blockIdx.x * 64;
    int n0 = blockIdx.y * 64;
    float acc[4][4];
#pragma unroll
    for (int r = 0; r < 4; r++)
#pragma unroll
        for (int c = 0; c < 4; c++) acc[r][c] = 0.0f;

    int la_row = tid >> 2, la_k = (tid & 3) * 4;  // A loader
    int lb_k = tid >> 4, lb_n = (tid & 15) * 4;   // B loader

    for (int k0 = 0; k0 < HID; k0 += 16) {
        float4 a4;
        int gr = m0 + la_row;
        if (gr < NN) a4 = *(const float4*)&A[(size_t)gr * HID + k0 + la_k];
        else a4 = make_float4(0.f, 0.f, 0.f, 0.f);
        As[la_k + 0][la_row] = a4.x;
        As[la_k + 1][la_row] = a4.y;
        As[la_k + 2][la_row] = a4.z;
        As[la_k + 3][la_row] = a4.w;
        float4 b4 = *(const float4*)&W[(size_t)(k0 + lb_k) * HID + n0 + lb_n];
        *(float4*)&Bs[lb_k][lb_n] = b4;
        __syncthreads();
#pragma unroll
        for (int kk = 0; kk < 16; kk++) {
            float4 av = *(const float4*)&As[kk][ty * 4];
            float4 bv = *(const float4*)&Bs[kk][tx * 4];
            float ar[4] = {av.x, av.y, av.z, av.w};
            float br[4] = {bv.x, bv.y, bv.z, bv.w};
#pragma unroll
            for (int r = 0; r < 4; r++)
#pragma unroll
                for (int c = 0; c < 4; c++) acc[r][c] += ar[r] * br[c];
        }
        __syncthreads();
    }
    float4 bb = *(const float4*)&b[n0 + tx * 4];
    float bbr[4] = {bb.x, bb.y, bb.z, bb.w};
#pragma unroll
    for (int r = 0; r < 4; r++) {
        int gr = m0 + ty * 4 + r;
        if (gr < NN) {
            float4 o;
            o.x = fmaxf(acc[r][0] + bbr[0], 0.0f);
            o.y = fmaxf(acc[r][1] + bbr[1], 0.0f);
            o.z = fmaxf(acc[r][2] + bbr[2], 0.0f);
            o.w = fmaxf(acc[r][3] + bbr[3], 0.0f);
            *(float4*)&C[(size_t)gr * HID + n0 + tx * 4] = o;
        }
    }
}

// ---------------- segment-max pooling (batch sorted) ------------------------
__global__ void k_pool(const int* __restrict__ batch) {
    const float* __restrict__ h = g_h1;  // final layer output lives in g_h1
    int f = threadIdx.x;                 // 0..127 feature
    int nbase = blockIdx.x * 128;
    int nend = min(nbase + 128, NN);
    int curg = -1;
    float m = 0.0f;
    for (int n = nbase; n < nend; ++n) {
        int g = batch[n];
        if (g != curg) {
            if (curg >= 0) atomicMax((int*)&g_pool[curg * HID + f], __float_as_int(m));
            curg = g;
            m = 0.0f;
        }
        m = fmaxf(m, h[(size_t)n * HID + f]);
    }
    if (curg >= 0) atomicMax((int*)&g_pool[curg * HID + f], __float_as_int(m));
}

// ---------------- final linear head -----------------------------------------
__global__ void k_final(const float* __restrict__ Wl, const float* __restrict__ bl,
                        float* __restrict__ out) {
    int wid = threadIdx.x >> 5, lane = threadIdx.x & 31;
    int g = blockIdx.x * 8 + wid;
    if (g >= NG) return;
    float a0 = 0.0f, a1 = 0.0f;
    for (int k = lane; k < HID; k += 32) {
        float p = g_pool[g * HID + k];
        a0 += p * Wl[k * 2 + 0];
        a1 += p * Wl[k * 2 + 1];
    }
#pragma unroll
    for (int off = 16; off > 0; off >>= 1) {
        a0 += __shfl_xor_sync(0xffffffffu, a0, off);
        a1 += __shfl_xor_sync(0xffffffffu, a1, off);
    }
    if (lane == 0) {
        out[g * 2 + 0] = a0 + bl[0];
        out[g * 2 + 1] = a1 + bl[1];
    }
}

// ---------------- launch -----------------------------------------------------
extern "C" void kernel_launch(void* const* d_in, const int* in_sizes, int n_in,
                              void* d_out, int out_size) {
    const float* x   = (const float*)d_in[0];
    const int* ei    = (const int*)d_in[1];
    const int* batch = (const int*)d_in[2];
    const float* W1  = (const float*)d_in[3];
    const float* b1  = (const float*)d_in[4];
    const float* W2  = (const float*)d_in[5];
    const float* b2  = (const float*)d_in[6];
    const float* W3  = (const float*)d_in[7];
    const float* b3  = (const float*)d_in[8];
    const float* Wl  = (const float*)d_in[9];
    const float* bl  = (const float*)d_in[10];
    float* out = (float*)d_out;

    const int* src = ei;
    const int* dst = ei + NE;

    // CSR build (counting sort by dst) + degree normalization
    k_init<<<(NN + 255) / 256, 256>>>();
    k_hist<<<(NE + 255) / 256, 256>>>(dst);
    k_dis<<<(NN + 255) / 256, 256>>>();
    k_scan1<<<SCAN_BLK, 1024>>>();
    k_scan2<<<1, 32>>>();
    k_scan3<<<SCAN_BLK, 1024>>>();
    k_scatter<<<(NE + 255) / 256, 256>>>(src, dst);

    // Layer 1: aggregate raw x (7 feats) then fused 7x128 GEMM + bias + relu
    k_layer1<<<(NN + 7) / 8, 256>>>(x, W1, b1);        // -> g_h1

    // Layer 2
    k_agg128<<<(NN + 7) / 8, 256>>>(0);                // g_h1 -> g_agg
    {
        dim3 grid((NN + 63) / 64, 2);
        k_gemm<<<grid, 256>>>(0, W2, b2);              // g_agg -> g_h2
    }
    // Layer 3
    k_agg128<<<(NN + 7) / 8, 256>>>(1);                // g_h2 -> g_agg
    {
        dim3 grid((NN + 63) / 64, 2);
        k_gemm<<<grid, 256>>>(1, W3, b3);              // g_agg -> g_h1
    }

    // Pool + head
    k_pool<<<(NN + 127) / 128, 128>>>(batch);
    k_final<<<(NG + 7) / 8, 256>>>(Wl, bl, out);
}

// round 5
// speedup vs baseline: 1.2628x; 1.2628x over previous
#include <cuda_runtime.h>
#include <cstdint>

#define NN 100000
#define NE 1600000
#define HID 128
#define INF_ 7
#define NG 512
#define SCAN_BLK ((NN + 1023) / 1024)

// ---------------- scratch (device globals: no allocation allowed) ----------
__device__ int   g_indeg[NN];
__device__ int   g_cursor[NN];
__device__ int   g_rowstart[NN];
__device__ float g_dis[NN];
__device__ int   g_csr_src[NE];
__device__ float g_csr_w[NE];
__device__ int   g_bsums[SCAN_BLK];
__device__ float g_h1[(size_t)NN * HID];
__device__ float g_h2[(size_t)NN * HID];
__device__ float g_agg[(size_t)NN * HID];
__device__ float g_pool[NG * HID];

// ---------------- graph preprocessing --------------------------------------
__global__ void k_init() {
    int i = blockIdx.x * blockDim.x + threadIdx.x;
    if (i < NN) { g_indeg[i] = 0; g_cursor[i] = 0; }
    if (i < NG * HID) g_pool[i] = 0.0f;
}

__global__ void k_hist(const int* __restrict__ dst) {
    int e = blockIdx.x * blockDim.x + threadIdx.x;
    if (e < NE) atomicAdd(&g_indeg[dst[e]], 1);
}

__global__ void k_dis() {
    int i = blockIdx.x * blockDim.x + threadIdx.x;
    if (i < NN) g_dis[i] = rsqrtf((float)(g_indeg[i] + 1));  // +1 self loop
}

__global__ void k_scan1() {
    __shared__ int s[1024];
    int tid = threadIdx.x;
    int i = blockIdx.x * 1024 + tid;
    int v = (i < NN) ? g_indeg[i] : 0;
    s[tid] = v;
    __syncthreads();
    for (int off = 1; off < 1024; off <<= 1) {
        int t = (tid >= off) ? s[tid - off] : 0;
        __syncthreads();
        s[tid] += t;
        __syncthreads();
    }
    if (i < NN) g_rowstart[i] = s[tid] - v;  // exclusive
    if (tid == 1023) g_bsums[blockIdx.x] = s[1023];
}

__global__ void k_scan2() {
    if (threadIdx.x == 0) {
        int acc = 0;
        for (int b = 0; b < SCAN_BLK; ++b) {
            int v = g_bsums[b];
            g_bsums[b] = acc;
            acc += v;
        }
    }
}

__global__ void k_scan3() {
    int i = blockIdx.x * 1024 + threadIdx.x;
    if (i < NN) g_rowstart[i] += g_bsums[blockIdx.x];
}

__global__ void k_scatter(const int* __restrict__ src, const int* __restrict__ dst) {
    int e = blockIdx.x * blockDim.x + threadIdx.x;
    if (e >= NE) return;
    int s = src[e], d = dst[e];
    int pos = atomicAdd(&g_cursor[d], 1);
    int idx = g_rowstart[d] + pos;
    g_csr_src[idx] = s;
    g_csr_w[idx] = g_dis[s] * g_dis[d];
}

// ---------------- layer 1: aggregate x (7 feats) fused with 7x128 GEMM -----
__global__ void k_layer1(const float* __restrict__ x, const float* __restrict__ W1,
                         const float* __restrict__ b1) {
    __shared__ float sW[INF_ * HID];
    __shared__ float sb[HID];
    int tid = threadIdx.x;
    for (int j = tid; j < INF_ * HID; j += blockDim.x) sW[j] = W1[j];
    if (tid < HID) sb[tid] = b1[tid];
    __syncthreads();

    int wid = tid >> 5, lane = tid & 31;
    int i = blockIdx.x * 8 + wid;
    if (i >= NN) return;

    int start = g_rowstart[i], len = g_indeg[i];
    float acc[INF_];
#pragma unroll
    for (int k = 0; k < INF_; k++) acc[k] = 0.0f;

    for (int e = start + lane; e < start + len; e += 32) {
        int s = g_csr_src[e];
        float w = g_csr_w[e];
        const float* xs = x + (size_t)s * INF_;
#pragma unroll
        for (int k = 0; k < INF_; k++) acc[k] += w * xs[k];
    }
#pragma unroll
    for (int k = 0; k < INF_; k++) {
#pragma unroll
        for (int off = 16; off > 0; off >>= 1)
            acc[k] += __shfl_xor_sync(0xffffffffu, acc[k], off);
    }
    float d = g_dis[i];
    float sw = d * d;
    const float* xi = x + (size_t)i * INF_;
#pragma unroll
    for (int k = 0; k < INF_; k++) acc[k] += sw * xi[k];

    int j0 = lane * 4;
    float ov[4];
#pragma unroll
    for (int j = 0; j < 4; j++) {
        float v = sb[j0 + j];
#pragma unroll
        for (int k = 0; k < INF_; k++) v += acc[k] * sW[k * HID + j0 + j];
        ov[j] = fmaxf(v, 0.0f);
    }
    *(float4*)&g_h1[(size_t)i * HID + j0] = make_float4(ov[0], ov[1], ov[2], ov[3]);
}

// ---------------- 128-feature CSR gather-aggregate -------------------------
__global__ void k_agg128(int src_sel) {
    const float* __restrict__ h = (src_sel == 0) ? g_h1 : g_h2;
    int wid = threadIdx.x >> 5, lane = threadIdx.x & 31;
    int i = blockIdx.x * 8 + wid;
    if (i >= NN) return;
    int start = g_rowstart[i], len = g_indeg[i];
    float d = g_dis[i];
    float sw = d * d;
    float4 acc = *(const float4*)&h[(size_t)i * HID + lane * 4];
    acc.x *= sw; acc.y *= sw; acc.z *= sw; acc.w *= sw;
    int end = start + len;
#pragma unroll 4
    for (int e = start; e < end; ++e) {
        int s = g_csr_src[e];
        float w = g_csr_w[e];
        float4 v = *(const float4*)&h[(size_t)s * HID + lane * 4];
        acc.x += w * v.x; acc.y += w * v.y; acc.z += w * v.z; acc.w += w * v.w;
    }
    *(float4*)&g_agg[(size_t)i * HID + lane * 4] = acc;
}

// ---------------- tf32 tensor-core GEMM: C = relu(g_agg @ W + b) -----------
__device__ __forceinline__ uint32_t f2tf32(float f) {
    uint32_t u;
    asm("cvt.rna.tf32.f32 %0, %1;" : "=r"(u) : "f"(f));
    return u;
}

__device__ __forceinline__ void mma_tf32(float& d0, float& d1, float& d2, float& d3,
                                         uint32_t a0, uint32_t a1, uint32_t a2, uint32_t a3,
                                         uint32_t b0, uint32_t b1) {
    asm volatile(
        "mma.sync.aligned.m16n8k8.row.col.f32.tf32.tf32.f32 "
        "{%0,%1,%2,%3}, {%4,%5,%6,%7}, {%8,%9}, {%0,%1,%2,%3};"
        : "+f"(d0), "+f"(d1), "+f"(d2), "+f"(d3)
        : "r"(a0), "r"(a1), "r"(a2), "r"(a3), "r"(b0), "r"(b1));
}

// Block: 256 threads (8 warps). Each block computes 128 rows x 128 cols.
// Each warp: 16 rows x 128 cols. A-fragments (16 k-steps) cached in registers
// across both 64-col halves. B repacked into smem in fragment order so each
// HMMA needs exactly one conflict-free LDS.64.
__global__ __launch_bounds__(256, 2) void k_gemm_tc(int out_sel,
                                                    const float* __restrict__ W,
                                                    const float* __restrict__ b) {
    float* __restrict__ C = (out_sel == 0) ? g_h2 : g_h1;
    const float* __restrict__ A = g_agg;
    __shared__ float2 sB[8][16][32];  // [n_frag][k_step][lane], tf32 bit patterns
    __shared__ float sb[HID];

    int tid = threadIdx.x;
    int wid = tid >> 5, lane = tid & 31;
    int grp = lane >> 2, t4 = lane & 3;
    if (tid < HID) sb[tid] = b[tid];

    int rbase = blockIdx.x * 128 + wid * 16;
    int r0 = rbase + grp;
    int r1 = rbase + grp + 8;
    int r0c = (r0 < NN) ? r0 : (NN - 1);
    int r1c = (r1 < NN) ? r1 : (NN - 1);

    // A fragments: 16 k-steps x 4 regs, loaded once from L2, converted to tf32.
    uint32_t areg[16][4];
#pragma unroll
    for (int ks = 0; ks < 16; ks++) {
        int c = ks * 8 + t4;
        areg[ks][0] = f2tf32(A[(size_t)r0c * HID + c]);
        areg[ks][1] = f2tf32(A[(size_t)r1c * HID + c]);
        areg[ks][2] = f2tf32(A[(size_t)r0c * HID + c + 4]);
        areg[ks][3] = f2tf32(A[(size_t)r1c * HID + c + 4]);
    }

#pragma unroll
    for (int half = 0; half < 2; half++) {
        int nbase = half * 64;
        __syncthreads();  // previous-half LDS done before refill
        // Repack W[k][n] into per-(nf,ks,lane) fragment pairs (b0 = k, b1 = k+4).
        for (int idx = tid; idx < 8 * 16 * 32; idx += 256) {
            int l = idx & 31;
            int ks = (idx >> 5) & 15;
            int nf = idx >> 9;
            int kk = ks * 8 + (l & 3);
            int nn = nbase + nf * 8 + (l >> 2);
            float2 v;
            v.x = __uint_as_float(f2tf32(W[kk * HID + nn]));
            v.y = __uint_as_float(f2tf32(W[(kk + 4) * HID + nn]));
            sB[nf][ks][l] = v;
        }
        __syncthreads();

        float cacc[8][4];
#pragma unroll
        for (int nf = 0; nf < 8; nf++)
#pragma unroll
            for (int q = 0; q < 4; q++) cacc[nf][q] = 0.0f;

#pragma unroll
        for (int ks = 0; ks < 16; ks++) {
#pragma unroll
            for (int nf = 0; nf < 8; nf++) {
                float2 bv = sB[nf][ks][lane];
                mma_tf32(cacc[nf][0], cacc[nf][1], cacc[nf][2], cacc[nf][3],
                         areg[ks][0], areg[ks][1], areg[ks][2], areg[ks][3],
                         __float_as_uint(bv.x), __float_as_uint(bv.y));
            }
        }

        // Epilogue: bias + relu + store
#pragma unroll
        for (int nf = 0; nf < 8; nf++) {
            int col = nbase + nf * 8 + 2 * t4;
            float bb0 = sb[col], bb1 = sb[col + 1];
            if (r0 < NN) {
                float2 o;
                o.x = fmaxf(cacc[nf][0] + bb0, 0.0f);
                o.y = fmaxf(cacc[nf][1] + bb1, 0.0f);
                *(float2*)&C[(size_t)r0 * HID + col] = o;
            }
            if (r1 < NN) {
                float2 o;
                o.x = fmaxf(cacc[nf][2] + bb0, 0.0f);
                o.y = fmaxf(cacc[nf][3] + bb1, 0.0f);
                *(float2*)&C[(size_t)r1 * HID + col] = o;
            }
        }
    }
}

// ---------------- segment-max pooling (batch sorted) ------------------------
__global__ void k_pool(const int* __restrict__ batch) {
    const float* __restrict__ h = g_h1;  // final layer output lives in g_h1
    int f = threadIdx.x;                 // 0..127 feature
    int nbase = blockIdx.x * 128;
    int nend = min(nbase + 128, NN);
    int curg = -1;
    float m = 0.0f;
    for (int n = nbase; n < nend; ++n) {
        int g = batch[n];
        if (g != curg) {
            if (curg >= 0) atomicMax((int*)&g_pool[curg * HID + f], __float_as_int(m));
            curg = g;
            m = 0.0f;
        }
        m = fmaxf(m, h[(size_t)n * HID + f]);
    }
    if (curg >= 0) atomicMax((int*)&g_pool[curg * HID + f], __float_as_int(m));
}

// ---------------- final linear head -----------------------------------------
__global__ void k_final(const float* __restrict__ Wl, const float* __restrict__ bl,
                        float* __restrict__ out) {
    int wid = threadIdx.x >> 5, lane = threadIdx.x & 31;
    int g = blockIdx.x * 8 + wid;
    if (g >= NG) return;
    float a0 = 0.0f, a1 = 0.0f;
    for (int k = lane; k < HID; k += 32) {
        float p = g_pool[g * HID + k];
        a0 += p * Wl[k * 2 + 0];
        a1 += p * Wl[k * 2 + 1];
    }
#pragma unroll
    for (int off = 16; off > 0; off >>= 1) {
        a0 += __shfl_xor_sync(0xffffffffu, a0, off);
        a1 += __shfl_xor_sync(0xffffffffu, a1, off);
    }
    if (lane == 0) {
        out[g * 2 + 0] = a0 + bl[0];
        out[g * 2 + 1] = a1 + bl[1];
    }
}

// ---------------- launch -----------------------------------------------------
extern "C" void kernel_launch(void* const* d_in, const int* in_sizes, int n_in,
                              void* d_out, int out_size) {
    const float* x   = (const float*)d_in[0];
    const int* ei    = (const int*)d_in[1];
    const int* batch = (const int*)d_in[2];
    const float* W1  = (const float*)d_in[3];
    const float* b1  = (const float*)d_in[4];
    const float* W2  = (const float*)d_in[5];
    const float* b2  = (const float*)d_in[6];
    const float* W3  = (const float*)d_in[7];
    const float* b3  = (const float*)d_in[8];
    const float* Wl  = (const float*)d_in[9];
    const float* bl  = (const float*)d_in[10];
    float* out = (float*)d_out;

    const int* src = ei;
    const int* dst = ei + NE;

    // CSR build (counting sort by dst) + degree normalization
    k_init<<<(NN + 255) / 256, 256>>>();
    k_hist<<<(NE + 255) / 256, 256>>>(dst);
    k_dis<<<(NN + 255) / 256, 256>>>();
    k_scan1<<<SCAN_BLK, 1024>>>();
    k_scan2<<<1, 32>>>();
    k_scan3<<<SCAN_BLK, 1024>>>();
    k_scatter<<<(NE + 255) / 256, 256>>>(src, dst);

    // Layer 1: aggregate raw x (7 feats) then fused 7x128 GEMM + bias + relu
    k_layer1<<<(NN + 7) / 8, 256>>>(x, W1, b1);        // -> g_h1

    // Layer 2
    k_agg128<<<(NN + 7) / 8, 256>>>(0);                // g_h1 -> g_agg
    k_gemm_tc<<<(NN + 127) / 128, 256>>>(0, W2, b2);   // g_agg -> g_h2

    // Layer 3
    k_agg128<<<(NN + 7) / 8, 256>>>(1);                // g_h2 -> g_agg
    k_gemm_tc<<<(NN + 127) / 128, 256>>>(1, W3, b3);   // g_agg -> g_h1

    // Pool + head
    k_pool<<<(NN + 127) / 128, 128>>>(batch);
    k_final<<<(NG + 7) / 8, 256>>>(Wl, bl, out);
}

// round 9
// speedup vs baseline: 1.3484x; 1.0678x over previous
#include <cuda_runtime.h>
#include <cuda_fp16.h>
#include <cstdint>

#define NN 100000
#define NE 1600000
#define HID 128
#define INF_ 7
#define NG 512
#define SCAN_BLK ((NN + 1023) / 1024)

// ---------------- scratch (device globals: no allocation allowed) ----------
__device__ int    g_indeg[NN];
__device__ int    g_cursor[NN];
__device__ int    g_rowstart[NN];
__device__ float  g_dis[NN];
__device__ int    g_csr_src[NE];
__device__ float  g_csr_w[NE];
__device__ int    g_bsums[SCAN_BLK];
__device__ __half g_h1[(size_t)NN * HID];   // hidden features stored fp16 (gather operand)
__device__ __half g_h2[(size_t)NN * HID];
__device__ float  g_agg[(size_t)NN * HID];  // fp32 aggregation accumulator
__device__ float  g_pool[NG * HID];

// ---------------- graph preprocessing --------------------------------------
__global__ void k_init() {
    int i = blockIdx.x * blockDim.x + threadIdx.x;
    if (i < NN) { g_indeg[i] = 0; g_cursor[i] = 0; }
    if (i < NG * HID) g_pool[i] = 0.0f;
}

__global__ void k_hist(const int* __restrict__ dst) {
    int e = blockIdx.x * blockDim.x + threadIdx.x;
    if (e < NE) atomicAdd(&g_indeg[dst[e]], 1);
}

__global__ void k_dis() {
    int i = blockIdx.x * blockDim.x + threadIdx.x;
    if (i < NN) g_dis[i] = rsqrtf((float)(g_indeg[i] + 1));  // +1 self loop
}

__global__ void k_scan1() {
    __shared__ int s[1024];
    int tid = threadIdx.x;
    int i = blockIdx.x * 1024 + tid;
    int v = (i < NN) ? g_indeg[i] : 0;
    s[tid] = v;
    __syncthreads();
    for (int off = 1; off < 1024; off <<= 1) {
        int t = (tid >= off) ? s[tid - off] : 0;
        __syncthreads();
        s[tid] += t;
        __syncthreads();
    }
    if (i < NN) g_rowstart[i] = s[tid] - v;  // exclusive
    if (tid == 1023) g_bsums[blockIdx.x] = s[1023];
}

__global__ void k_scan2() {
    if (threadIdx.x == 0) {
        int acc = 0;
        for (int b = 0; b < SCAN_BLK; ++b) {
            int v = g_bsums[b];
            g_bsums[b] = acc;
            acc += v;
        }
    }
}

__global__ void k_scan3() {
    int i = blockIdx.x * 1024 + threadIdx.x;
    if (i < NN) g_rowstart[i] += g_bsums[blockIdx.x];
}

__global__ void k_scatter(const int* __restrict__ src, const int* __restrict__ dst) {
    int e = blockIdx.x * blockDim.x + threadIdx.x;
    if (e >= NE) return;
    int s = src[e], d = dst[e];
    int pos = atomicAdd(&g_cursor[d], 1);
    int idx = g_rowstart[d] + pos;
    g_csr_src[idx] = s;
    g_csr_w[idx] = g_dis[s] * g_dis[d];
}

// ---------------- layer 1: aggregate x (7 feats) fused with 7x128 GEMM -----
__global__ void k_layer1(const float* __restrict__ x, const float* __restrict__ W1,
                         const float* __restrict__ b1) {
    __shared__ float sW[INF_ * HID];
    __shared__ float sb[HID];
    int tid = threadIdx.x;
    for (int j = tid; j < INF_ * HID; j += blockDim.x) sW[j] = W1[j];
    if (tid < HID) sb[tid] = b1[tid];
    __syncthreads();

    int wid = tid >> 5, lane = tid & 31;
    int i = blockIdx.x * 8 + wid;
    if (i >= NN) return;

    int start = g_rowstart[i], len = g_indeg[i];
    float acc[INF_];
#pragma unroll
    for (int k = 0; k < INF_; k++) acc[k] = 0.0f;

    for (int e = start + lane; e < start + len; e += 32) {
        int s = g_csr_src[e];
        float w = g_csr_w[e];
        const float* xs = x + (size_t)s * INF_;
#pragma unroll
        for (int k = 0; k < INF_; k++) acc[k] += w * xs[k];
    }
#pragma unroll
    for (int k = 0; k < INF_; k++) {
#pragma unroll
        for (int off = 16; off > 0; off >>= 1)
            acc[k] += __shfl_xor_sync(0xffffffffu, acc[k], off);
    }
    float d = g_dis[i];
    float sw = d * d;
    const float* xi = x + (size_t)i * INF_;
#pragma unroll
    for (int k = 0; k < INF_; k++) acc[k] += sw * xi[k];

    int j0 = lane * 4;
    float ov[4];
#pragma unroll
    for (int j = 0; j < 4; j++) {
        float v = sb[j0 + j];
#pragma unroll
        for (int k = 0; k < INF_; k++) v += acc[k] * sW[k * HID + j0 + j];
        ov[j] = fmaxf(v, 0.0f);
    }
    __half2 p0 = __floats2half2_rn(ov[0], ov[1]);
    __half2 p1 = __floats2half2_rn(ov[2], ov[3]);
    uint2 pk;
    pk.x = *(uint32_t*)&p0;
    pk.y = *(uint32_t*)&p1;
    *(uint2*)&g_h1[(size_t)i * HID + j0] = pk;
}

// ---------------- 128-feature CSR gather-aggregate (fp16 gather) -----------
__global__ void k_agg128(int src_sel) {
    const __half* __restrict__ h = (src_sel == 0) ? g_h1 : g_h2;
    int wid = threadIdx.x >> 5, lane = threadIdx.x & 31;
    int i = blockIdx.x * 8 + wid;
    if (i >= NN) return;
    int start = g_rowstart[i], len = g_indeg[i];
    float d = g_dis[i];
    float sw = d * d;

    uint2 self = *(const uint2*)&h[(size_t)i * HID + lane * 4];
    float2 s0 = __half22float2(*(__half2*)&self.x);
    float2 s1 = __half22float2(*(__half2*)&self.y);
    float4 acc = make_float4(sw * s0.x, sw * s0.y, sw * s1.x, sw * s1.y);

    int end = start + len;
#pragma unroll 4
    for (int e = start; e < end; ++e) {
        int s = g_csr_src[e];
        float w = g_csr_w[e];
        uint2 raw = *(const uint2*)&h[(size_t)s * HID + lane * 4];
        float2 v0 = __half22float2(*(__half2*)&raw.x);
        float2 v1 = __half22float2(*(__half2*)&raw.y);
        acc.x += w * v0.x; acc.y += w * v0.y; acc.z += w * v1.x; acc.w += w * v1.y;
    }
    *(float4*)&g_agg[(size_t)i * HID + lane * 4] = acc;
}

// ---------------- tf32 tensor-core GEMM: C = relu(g_agg @ W + b) -----------
__device__ __forceinline__ uint32_t f2tf32(float f) {
    uint32_t u;
    asm("cvt.rna.tf32.f32 %0, %1;" : "=r"(u) : "f"(f));
    return u;
}

__device__ __forceinline__ void mma_tf32(float& d0, float& d1, float& d2, float& d3,
                                         uint32_t a0, uint32_t a1, uint32_t a2, uint32_t a3,
                                         uint32_t b0, uint32_t b1) {
    asm volatile(
        "mma.sync.aligned.m16n8k8.row.col.f32.tf32.tf32.f32 "
        "{%0,%1,%2,%3}, {%4,%5,%6,%7}, {%8,%9}, {%0,%1,%2,%3};"
        : "+f"(d0), "+f"(d1), "+f"(d2), "+f"(d3)
        : "r"(a0), "r"(a1), "r"(a2), "r"(a3), "r"(b0), "r"(b1));
}

// Block: 256 threads (8 warps). Each warp: 16 rows x 128 cols, A-fragments
// register-cached across both N-halves. Output written as fp16.
__global__ __launch_bounds__(256, 2) void k_gemm_tc(int out_sel,
                                                    const float* __restrict__ W,
                                                    const float* __restrict__ b) {
    __half* __restrict__ C = (out_sel == 0) ? g_h2 : g_h1;
    const float* __restrict__ A = g_agg;
    __shared__ float2 sB[8][16][32];  // [n_frag][k_step][lane], tf32 bit patterns
    __shared__ float sb[HID];

    int tid = threadIdx.x;
    int wid = tid >> 5, lane = tid & 31;
    int grp = lane >> 2, t4 = lane & 3;
    if (tid < HID) sb[tid] = b[tid];

    int rbase = blockIdx.x * 128 + wid * 16;
    int r0 = rbase + grp;
    int r1 = rbase + grp + 8;
    int r0c = (r0 < NN) ? r0 : (NN - 1);
    int r1c = (r1 < NN) ? r1 : (NN - 1);

    uint32_t areg[16][4];
#pragma unroll
    for (int ks = 0; ks < 16; ks++) {
        int c = ks * 8 + t4;
        areg[ks][0] = f2tf32(A[(size_t)r0c * HID + c]);
        areg[ks][1] = f2tf32(A[(size_t)r1c * HID + c]);
        areg[ks][2] = f2tf32(A[(size_t)r0c * HID + c + 4]);
        areg[ks][3] = f2tf32(A[(size_t)r1c * HID + c + 4]);
    }

#pragma unroll
    for (int half = 0; half < 2; half++) {
        int nbase = half * 64;
        __syncthreads();
        for (int idx = tid; idx < 8 * 16 * 32; idx += 256) {
            int l = idx & 31;
            int ks = (idx >> 5) & 15;
            int nf = idx >> 9;
            int kk = ks * 8 + (l & 3);
            int nn = nbase + nf * 8 + (l >> 2);
            float2 v;
            v.x = __uint_as_float(f2tf32(W[kk * HID + nn]));
            v.y = __uint_as_float(f2tf32(W[(kk + 4) * HID + nn]));
            sB[nf][ks][l] = v;
        }
        __syncthreads();

        float cacc[8][4];
#pragma unroll
        for (int nf = 0; nf < 8; nf++)
#pragma unroll
            for (int q = 0; q < 4; q++) cacc[nf][q] = 0.0f;

#pragma unroll
        for (int ks = 0; ks < 16; ks++) {
#pragma unroll
            for (int nf = 0; nf < 8; nf++) {
                float2 bv = sB[nf][ks][lane];
                mma_tf32(cacc[nf][0], cacc[nf][1], cacc[nf][2], cacc[nf][3],
                         areg[ks][0], areg[ks][1], areg[ks][2], areg[ks][3],
                         __float_as_uint(bv.x), __float_as_uint(bv.y));
            }
        }

#pragma unroll
        for (int nf = 0; nf < 8; nf++) {
            int col = nbase + nf * 8 + 2 * t4;
            float bb0 = sb[col], bb1 = sb[col + 1];
            if (r0 < NN) {
                __half2 o = __floats2half2_rn(fmaxf(cacc[nf][0] + bb0, 0.0f),
                                              fmaxf(cacc[nf][1] + bb1, 0.0f));
                *(__half2*)&C[(size_t)r0 * HID + col] = o;
            }
            if (r1 < NN) {
                __half2 o = __floats2half2_rn(fmaxf(cacc[nf][2] + bb0, 0.0f),
                                              fmaxf(cacc[nf][3] + bb1, 0.0f));
                *(__half2*)&C[(size_t)r1 * HID + col] = o;
            }
        }
    }
}

// ---------------- segment-max pooling (batch sorted) ------------------------
__global__ void k_pool(const int* __restrict__ batch) {
    const __half* __restrict__ h = g_h1;  // final layer output lives in g_h1
    int f = threadIdx.x;                  // 0..127 feature
    int nbase = blockIdx.x * 128;
    int nend = min(nbase + 128, NN);
    int curg = -1;
    float m = 0.0f;
    for (int n = nbase; n < nend; ++n) {
        int g = batch[n];
        if (g != curg) {
            if (curg >= 0) atomicMax((int*)&g_pool[curg * HID + f], __float_as_int(m));
            curg = g;
            m = 0.0f;
        }
        m = fmaxf(m, __half2float(h[(size_t)n * HID + f]));
    }
    if (curg >= 0) atomicMax((int*)&g_pool[curg * HID + f], __float_as_int(m));
}

// ---------------- final linear head -----------------------------------------
__global__ void k_final(const float* __restrict__ Wl, const float* __restrict__ bl,
                        float* __restrict__ out) {
    int wid = threadIdx.x >> 5, lane = threadIdx.x & 31;
    int g = blockIdx.x * 8 + wid;
    if (g >= NG) return;
    float a0 = 0.0f, a1 = 0.0f;
    for (int k = lane; k < HID; k += 32) {
        float p = g_pool[g * HID + k];
        a0 += p * Wl[k * 2 + 0];
        a1 += p * Wl[k * 2 + 1];
    }
#pragma unroll
    for (int off = 16; off > 0; off >>= 1) {
        a0 += __shfl_xor_sync(0xffffffffu, a0, off);
        a1 += __shfl_xor_sync(0xffffffffu, a1, off);
    }
    if (lane == 0) {
        out[g * 2 + 0] = a0 + bl[0];
        out[g * 2 + 1] = a1 + bl[1];
    }
}

// ---------------- launch -----------------------------------------------------
extern "C" void kernel_launch(void* const* d_in, const int* in_sizes, int n_in,
                              void* d_out, int out_size) {
    const float* x   = (const float*)d_in[0];
    const int* ei    = (const int*)d_in[1];
    const int* batch = (const int*)d_in[2];
    const float* W1  = (const float*)d_in[3];
    const float* b1  = (const float*)d_in[4];
    const float* W2  = (const float*)d_in[5];
    const float* b2  = (const float*)d_in[6];
    const float* W3  = (const float*)d_in[7];
    const float* b3  = (const float*)d_in[8];
    const float* Wl  = (const float*)d_in[9];
    const float* bl  = (const float*)d_in[10];
    float* out = (float*)d_out;

    const int* src = ei;
    const int* dst = ei + NE;

    // CSR build (counting sort by dst) + degree normalization
    k_init<<<(NN + 255) / 256, 256>>>();
    k_hist<<<(NE + 255) / 256, 256>>>(dst);
    k_dis<<<(NN + 255) / 256, 256>>>();
    k_scan1<<<SCAN_BLK, 1024>>>();
    k_scan2<<<1, 32>>>();
    k_scan3<<<SCAN_BLK, 1024>>>();
    k_scatter<<<(NE + 255) / 256, 256>>>(src, dst);

    // Layer 1: aggregate raw x (7 feats) then fused 7x128 GEMM + bias + relu
    k_layer1<<<(NN + 7) / 8, 256>>>(x, W1, b1);        // -> g_h1 (fp16)

    // Layer 2
    k_agg128<<<(NN + 7) / 8, 256>>>(0);                // g_h1 -> g_agg (fp32)
    k_gemm_tc<<<(NN + 127) / 128, 256>>>(0, W2, b2);   // g_agg -> g_h2 (fp16)

    // Layer 3
    k_agg128<<<(NN + 7) / 8, 256>>>(1);                // g_h2 -> g_agg
    k_gemm_tc<<<(NN + 127) / 128, 256>>>(1, W3, b3);   // g_agg -> g_h1

    // Pool + head
    k_pool<<<(NN + 127) / 128, 128>>>(batch);
    k_final<<<(NG + 7) / 8, 256>>>(Wl, bl, out);
}

// round 11
// speedup vs baseline: 1.4901x; 1.1051x over previous
#include <cuda_runtime.h>
#include <cuda_fp16.h>
#include <cstdint>

#define NN 100000
#define NE 1600000
#define HID 128
#define INF_ 7
#define NG 512
#define SCAN_BLK ((NN + 1023) / 1024)

// ---------------- scratch (device globals: no allocation allowed) ----------
__device__ int    g_indeg[NN];
__device__ int    g_cursor[NN];
__device__ int    g_rowstart[NN];   // block-local exclusive scan; add g_bsums[i>>10]
__device__ float  g_dis[NN];
__device__ int    g_csr_src[NE];
__device__ float  g_csr_w[NE];
__device__ int    g_bsums[SCAN_BLK];
__device__ __half g_h1[(size_t)NN * HID];   // hidden features fp16 (gather operand)
__device__ __half g_h2[(size_t)NN * HID];
__device__ __half g_agg[(size_t)NN * HID];  // fp16 aggregated features (GEMM A)
__device__ float  g_pool[NG * HID];

__device__ __forceinline__ int rowstart_of(int i) {
    return g_rowstart[i] + g_bsums[i >> 10];
}

// ---------------- graph preprocessing --------------------------------------
__global__ void k_init() {
    int i = blockIdx.x * blockDim.x + threadIdx.x;
    if (i < NN) { g_indeg[i] = 0; g_cursor[i] = 0; }
    if (i < NG * HID) g_pool[i] = 0.0f;
}

__global__ void k_hist(const int* __restrict__ dst) {
    int e = blockIdx.x * blockDim.x + threadIdx.x;
    if (e < NE) atomicAdd(&g_indeg[dst[e]], 1);
}

// block-local exclusive scan of indeg + per-node rsqrt(deg+1)
__global__ void k_scan1() {
    __shared__ int s[1024];
    int tid = threadIdx.x;
    int i = blockIdx.x * 1024 + tid;
    int v = (i < NN) ? g_indeg[i] : 0;
    if (i < NN) g_dis[i] = rsqrtf((float)(v + 1));  // +1 self loop
    s[tid] = v;
    __syncthreads();
    for (int off = 1; off < 1024; off <<= 1) {
        int t = (tid >= off) ? s[tid - off] : 0;
        __syncthreads();
        s[tid] += t;
        __syncthreads();
    }
    if (i < NN) g_rowstart[i] = s[tid] - v;  // exclusive (block-local)
    if (tid == 1023) g_bsums[blockIdx.x] = s[1023];
}

__global__ void k_scan2() {
    if (threadIdx.x == 0) {
        int acc = 0;
        for (int b = 0; b < SCAN_BLK; ++b) {
            int v = g_bsums[b];
            g_bsums[b] = acc;
            acc += v;
        }
    }
}

__global__ void k_scatter(const int* __restrict__ src, const int* __restrict__ dst) {
    int e = blockIdx.x * blockDim.x + threadIdx.x;
    if (e >= NE) return;
    int s = src[e], d = dst[e];
    int pos = atomicAdd(&g_cursor[d], 1);
    int idx = rowstart_of(d) + pos;
    g_csr_src[idx] = s;
    g_csr_w[idx] = g_dis[s] * g_dis[d];
}

// ---------------- layer 1: aggregate x (7 feats) fused with 7x128 GEMM -----
__global__ void k_layer1(const float* __restrict__ x, const float* __restrict__ W1,
                         const float* __restrict__ b1) {
    __shared__ float sW[INF_ * HID];
    __shared__ float sb[HID];
    int tid = threadIdx.x;
    for (int j = tid; j < INF_ * HID; j += blockDim.x) sW[j] = W1[j];
    if (tid < HID) sb[tid] = b1[tid];
    __syncthreads();

    int wid = tid >> 5, lane = tid & 31;
    int i = blockIdx.x * 8 + wid;
    if (i >= NN) return;

    int start = rowstart_of(i), len = g_indeg[i];
    float acc[INF_];
#pragma unroll
    for (int k = 0; k < INF_; k++) acc[k] = 0.0f;

    for (int e = start + lane; e < start + len; e += 32) {
        int s = g_csr_src[e];
        float w = g_csr_w[e];
        const float* xs = x + (size_t)s * INF_;
#pragma unroll
        for (int k = 0; k < INF_; k++) acc[k] += w * xs[k];
    }
#pragma unroll
    for (int k = 0; k < INF_; k++) {
#pragma unroll
        for (int off = 16; off > 0; off >>= 1)
            acc[k] += __shfl_xor_sync(0xffffffffu, acc[k], off);
    }
    float d = g_dis[i];
    float sw = d * d;
    const float* xi = x + (size_t)i * INF_;
#pragma unroll
    for (int k = 0; k < INF_; k++) acc[k] += sw * xi[k];

    int j0 = lane * 4;
    float ov[4];
#pragma unroll
    for (int j = 0; j < 4; j++) {
        float v = sb[j0 + j];
#pragma unroll
        for (int k = 0; k < INF_; k++) v += acc[k] * sW[k * HID + j0 + j];
        ov[j] = fmaxf(v, 0.0f);
    }
    __half2 p0 = __floats2half2_rn(ov[0], ov[1]);
    __half2 p1 = __floats2half2_rn(ov[2], ov[3]);
    uint2 pk;
    pk.x = *(uint32_t*)&p0;
    pk.y = *(uint32_t*)&p1;
    *(uint2*)&g_h1[(size_t)i * HID + j0] = pk;
}

// ---------------- 128-feature CSR gather-aggregate (fp16 in/out) -----------
__global__ void k_agg128(int src_sel) {
    const __half* __restrict__ h = (src_sel == 0) ? g_h1 : g_h2;
    int wid = threadIdx.x >> 5, lane = threadIdx.x & 31;
    int i = blockIdx.x * 8 + wid;
    if (i >= NN) return;
    int start = rowstart_of(i), len = g_indeg[i];
    float d = g_dis[i];
    float sw = d * d;

    uint2 self = *(const uint2*)&h[(size_t)i * HID + lane * 4];
    float2 s0 = __half22float2(*(__half2*)&self.x);
    float2 s1 = __half22float2(*(__half2*)&self.y);
    float4 acc = make_float4(sw * s0.x, sw * s0.y, sw * s1.x, sw * s1.y);

    int end = start + len;
#pragma unroll 4
    for (int e = start; e < end; ++e) {
        int s = g_csr_src[e];
        float w = g_csr_w[e];
        uint2 raw = *(const uint2*)&h[(size_t)s * HID + lane * 4];
        float2 v0 = __half22float2(*(__half2*)&raw.x);
        float2 v1 = __half22float2(*(__half2*)&raw.y);
        acc.x += w * v0.x; acc.y += w * v0.y; acc.z += w * v1.x; acc.w += w * v1.y;
    }
    __half2 p0 = __floats2half2_rn(acc.x, acc.y);
    __half2 p1 = __floats2half2_rn(acc.z, acc.w);
    uint2 pk;
    pk.x = *(uint32_t*)&p0;
    pk.y = *(uint32_t*)&p1;
    *(uint2*)&g_agg[(size_t)i * HID + lane * 4] = pk;
}

// ---------------- fp16 tensor-core GEMM: C = relu(g_agg @ W + b) -----------
__device__ __forceinline__ void mma_f16(float& d0, float& d1, float& d2, float& d3,
                                        uint32_t a0, uint32_t a1, uint32_t a2, uint32_t a3,
                                        uint32_t b0, uint32_t b1) {
    asm volatile(
        "mma.sync.aligned.m16n8k16.row.col.f32.f16.f16.f32 "
        "{%0,%1,%2,%3}, {%4,%5,%6,%7}, {%8,%9}, {%0,%1,%2,%3};"
        : "+f"(d0), "+f"(d1), "+f"(d2), "+f"(d3)
        : "r"(a0), "r"(a1), "r"(a2), "r"(a3), "r"(b0), "r"(b1));
}

// Block: 256 threads (8 warps). Each warp: 16 rows x 128 cols in ONE pass.
// A (fp16) fragments register-cached; W repacked to smem in exact
// m16n8k16 B-fragment order: one conflict-free LDS.64 per HMMA.
__global__ __launch_bounds__(256, 2) void k_gemm_tc(int out_sel,
                                                    const float* __restrict__ W,
                                                    const float* __restrict__ b) {
    __half* __restrict__ C = (out_sel == 0) ? g_h2 : g_h1;
    const __half* __restrict__ A = g_agg;
    __shared__ uint2 sB[16][8][32];  // [n_frag][k_step][lane] = {b0, b1}
    __shared__ float sb[HID];

    int tid = threadIdx.x;
    int wid = tid >> 5, lane = tid & 31;
    int grp = lane >> 2, t4 = lane & 3;
    if (tid < HID) sb[tid] = b[tid];

    // Repack W[k][n] (fp32 row-major) into fp16 B fragments.
    // b0 = {W[k0+2t4][n], W[k0+2t4+1][n]}, b1 = same at k+8.
    for (int idx = tid; idx < 16 * 8 * 32; idx += 256) {
        int l = idx & 31;
        int ks = (idx >> 5) & 7;
        int nf = idx >> 8;
        int kk = ks * 16 + 2 * (l & 3);
        int nn = nf * 8 + (l >> 2);
        __half2 v0 = __floats2half2_rn(W[kk * HID + nn], W[(kk + 1) * HID + nn]);
        __half2 v1 = __floats2half2_rn(W[(kk + 8) * HID + nn], W[(kk + 9) * HID + nn]);
        sB[nf][ks][l] = make_uint2(*(uint32_t*)&v0, *(uint32_t*)&v1);
    }

    int rbase = blockIdx.x * 128 + wid * 16;
    int r0 = rbase + grp;
    int r1 = rbase + grp + 8;
    int r0c = (r0 < NN) ? r0 : (NN - 1);
    int r1c = (r1 < NN) ? r1 : (NN - 1);

    // A fragments: 8 k-steps x 4 regs (each reg = 2 fp16), loaded once.
    uint32_t areg[8][4];
    int c0 = 2 * t4;
#pragma unroll
    for (int ks = 0; ks < 8; ks++) {
        int k0 = ks * 16;
        areg[ks][0] = *(const uint32_t*)&A[(size_t)r0c * HID + k0 + c0];
        areg[ks][1] = *(const uint32_t*)&A[(size_t)r1c * HID + k0 + c0];
        areg[ks][2] = *(const uint32_t*)&A[(size_t)r0c * HID + k0 + c0 + 8];
        areg[ks][3] = *(const uint32_t*)&A[(size_t)r1c * HID + k0 + c0 + 8];
    }
    __syncthreads();

    float cacc[16][4];
#pragma unroll
    for (int nf = 0; nf < 16; nf++)
#pragma unroll
        for (int q = 0; q < 4; q++) cacc[nf][q] = 0.0f;

#pragma unroll
    for (int ks = 0; ks < 8; ks++) {
#pragma unroll
        for (int nf = 0; nf < 16; nf++) {
            uint2 bv = sB[nf][ks][lane];
            mma_f16(cacc[nf][0], cacc[nf][1], cacc[nf][2], cacc[nf][3],
                    areg[ks][0], areg[ks][1], areg[ks][2], areg[ks][3],
                    bv.x, bv.y);
        }
    }

    // Epilogue: bias + relu + fp16 store
#pragma unroll
    for (int nf = 0; nf < 16; nf++) {
        int col = nf * 8 + 2 * t4;
        float bb0 = sb[col], bb1 = sb[col + 1];
        if (r0 < NN) {
            __half2 o = __floats2half2_rn(fmaxf(cacc[nf][0] + bb0, 0.0f),
                                          fmaxf(cacc[nf][1] + bb1, 0.0f));
            *(__half2*)&C[(size_t)r0 * HID + col] = o;
        }
        if (r1 < NN) {
            __half2 o = __floats2half2_rn(fmaxf(cacc[nf][2] + bb0, 0.0f),
                                          fmaxf(cacc[nf][3] + bb1, 0.0f));
            *(__half2*)&C[(size_t)r1 * HID + col] = o;
        }
    }
}

// ---------------- segment-max pooling (batch sorted) ------------------------
__global__ void k_pool(const int* __restrict__ batch) {
    const __half* __restrict__ h = g_h1;  // final layer output lives in g_h1
    int f = threadIdx.x;                  // 0..127 feature
    int nbase = blockIdx.x * 128;
    int nend = min(nbase + 128, NN);
    int curg = -1;
    float m = 0.0f;
    for (int n = nbase; n < nend; ++n) {
        int g = batch[n];
        if (g != curg) {
            if (curg >= 0) atomicMax((int*)&g_pool[curg * HID + f], __float_as_int(m));
            curg = g;
            m = 0.0f;
        }
        m = fmaxf(m, __half2float(h[(size_t)n * HID + f]));
    }
    if (curg >= 0) atomicMax((int*)&g_pool[curg * HID + f], __float_as_int(m));
}

// ---------------- final linear head -----------------------------------------
__global__ void k_final(const float* __restrict__ Wl, const float* __restrict__ bl,
                        float* __restrict__ out) {
    int wid = threadIdx.x >> 5, lane = threadIdx.x & 31;
    int g = blockIdx.x * 8 + wid;
    if (g >= NG) return;
    float a0 = 0.0f, a1 = 0.0f;
    for (int k = lane; k < HID; k += 32) {
        float p = g_pool[g * HID + k];
        a0 += p * Wl[k * 2 + 0];
        a1 += p * Wl[k * 2 + 1];
    }
#pragma unroll
    for (int off = 16; off > 0; off >>= 1) {
        a0 += __shfl_xor_sync(0xffffffffu, a0, off);
        a1 += __shfl_xor_sync(0xffffffffu, a1, off);
    }
    if (lane == 0) {
        out[g * 2 + 0] = a0 + bl[0];
        out[g * 2 + 1] = a1 + bl[1];
    }
}

// ---------------- launch -----------------------------------------------------
extern "C" void kernel_launch(void* const* d_in, const int* in_sizes, int n_in,
                              void* d_out, int out_size) {
    const float* x   = (const float*)d_in[0];
    const int* ei    = (const int*)d_in[1];
    const int* batch = (const int*)d_in[2];
    const float* W1  = (const float*)d_in[3];
    const float* b1  = (const float*)d_in[4];
    const float* W2  = (const float*)d_in[5];
    const float* b2  = (const float*)d_in[6];
    const float* W3  = (const float*)d_in[7];
    const float* b3  = (const float*)d_in[8];
    const float* Wl  = (const float*)d_in[9];
    const float* bl  = (const float*)d_in[10];
    float* out = (float*)d_out;

    const int* src = ei;
    const int* dst = ei + NE;

    // CSR build (counting sort by dst) + degree normalization
    k_init<<<(NN + 255) / 256, 256>>>();
    k_hist<<<(NE + 255) / 256, 256>>>(dst);
    k_scan1<<<SCAN_BLK, 1024>>>();   // also computes g_dis
    k_scan2<<<1, 32>>>();
    k_scatter<<<(NE + 255) / 256, 256>>>(src, dst);

    // Layer 1: aggregate raw x (7 feats) then fused 7x128 GEMM + bias + relu
    k_layer1<<<(NN + 7) / 8, 256>>>(x, W1, b1);        // -> g_h1 (fp16)

    // Layer 2
    k_agg128<<<(NN + 7) / 8, 256>>>(0);                // g_h1 -> g_agg (fp16)
    k_gemm_tc<<<(NN + 127) / 128, 256>>>(0, W2, b2);   // g_agg -> g_h2 (fp16)

    // Layer 3
    k_agg128<<<(NN + 7) / 8, 256>>>(1);                // g_h2 -> g_agg
    k_gemm_tc<<<(NN + 127) / 128, 256>>>(1, W3, b3);   // g_agg -> g_h1

    // Pool + head
    k_pool<<<(NN + 127) / 128, 128>>>(batch);
    k_final<<<(NG + 7) / 8, 256>>>(Wl, bl, out);
}

// round 12
// speedup vs baseline: 1.6374x; 1.0988x over previous
#include <cuda_runtime.h>
#include <cuda_fp16.h>
#include <cstdint>

#define NN 100000
#define NE 1600000
#define HID 128
#define INF_ 7
#define NG 512
#define SCAN_BLK ((NN + 1023) / 1024)

// ---------------- scratch (device globals: no allocation allowed) ----------
__device__ int    g_indeg[NN];
__device__ int    g_cursor[NN];
__device__ int    g_rowstart[NN];    // GLOBAL exclusive scan (lookback in k_scan1)
__device__ float  g_dis[NN];
__device__ int2   g_csr[NE];         // {src, __float_as_int(weight)}
__device__ int    g_aggpub[SCAN_BLK];// lookback: block aggregate + 1 (0 = not ready)
__device__ __half g_h1[(size_t)NN * HID];   // hidden features fp16 (gather operand)
__device__ __half g_h2[(size_t)NN * HID];
__device__ __half g_agg[(size_t)NN * HID];  // fp16 aggregated features (GEMM A)

// ---------------- graph preprocessing --------------------------------------
__global__ void k_init() {
    int i = blockIdx.x * blockDim.x + threadIdx.x;
    if (i < NN) { g_indeg[i] = 0; g_cursor[i] = 0; }
    if (i < SCAN_BLK) g_aggpub[i] = 0;
}

__global__ void k_hist(const int* __restrict__ dst) {
    int e = blockIdx.x * blockDim.x + threadIdx.x;
    if (e < NE) atomicAdd(&g_indeg[dst[e]], 1);
}

// Single-pass scan: block-local scan + decoupled lookback over block aggregates.
// All SCAN_BLK=98 blocks are co-resident (98 <= 148 SMs), so polling is safe.
__global__ void k_scan1() {
    __shared__ int s[1024];
    __shared__ int s_off;
    int tid = threadIdx.x;
    int bid = blockIdx.x;
    int i = bid * 1024 + tid;
    int v = (i < NN) ? g_indeg[i] : 0;
    if (i < NN) g_dis[i] = rsqrtf((float)(v + 1));  // +1 self loop
    s[tid] = v;
    __syncthreads();
    for (int off = 1; off < 1024; off <<= 1) {
        int t = (tid >= off) ? s[tid - off] : 0;
        __syncthreads();
        s[tid] += t;
        __syncthreads();
    }
    // publish this block's aggregate (+1 so 0 means "not ready")
    if (tid == 1023) atomicExch(&g_aggpub[bid], s[1023] + 1);
    if (tid == 0) s_off = 0;
    __syncthreads();
    // lookback: thread t polls predecessor t's aggregate
    if (tid < bid) {
        volatile int* p = &g_aggpub[tid];
        int a;
        do { a = *p; } while (a == 0);
        atomicAdd(&s_off, a - 1);
    }
    __syncthreads();
    if (i < NN) g_rowstart[i] = s_off + s[tid] - v;  // global exclusive scan
}

__global__ void k_scatter(const int* __restrict__ src, const int* __restrict__ dst) {
    int e = blockIdx.x * blockDim.x + threadIdx.x;
    if (e >= NE) return;
    int s = src[e], d = dst[e];
    int pos = atomicAdd(&g_cursor[d], 1);
    g_csr[g_rowstart[d] + pos] = make_int2(s, __float_as_int(g_dis[s] * g_dis[d]));
}

// ---------------- layer 1: aggregate x (7 feats) fused with 7x128 GEMM -----
__global__ void k_layer1(const float* __restrict__ x, const float* __restrict__ W1,
                         const float* __restrict__ b1) {
    __shared__ float sW[INF_ * HID];
    __shared__ float sb[HID];
    int tid = threadIdx.x;
    for (int j = tid; j < INF_ * HID; j += blockDim.x) sW[j] = W1[j];
    if (tid < HID) sb[tid] = b1[tid];
    __syncthreads();

    int wid = tid >> 5, lane = tid & 31;
    int i = blockIdx.x * 8 + wid;
    if (i >= NN) return;

    int start = g_rowstart[i], len = g_indeg[i];
    float acc[INF_];
#pragma unroll
    for (int k = 0; k < INF_; k++) acc[k] = 0.0f;

    for (int e = start + lane; e < start + len; e += 32) {
        int2 ed = g_csr[e];
        float w = __int_as_float(ed.y);
        const float* xs = x + (size_t)ed.x * INF_;
#pragma unroll
        for (int k = 0; k < INF_; k++) acc[k] += w * xs[k];
    }
#pragma unroll
    for (int k = 0; k < INF_; k++) {
#pragma unroll
        for (int off = 16; off > 0; off >>= 1)
            acc[k] += __shfl_xor_sync(0xffffffffu, acc[k], off);
    }
    float d = g_dis[i];
    float sw = d * d;
    const float* xi = x + (size_t)i * INF_;
#pragma unroll
    for (int k = 0; k < INF_; k++) acc[k] += sw * xi[k];

    int j0 = lane * 4;
    float ov[4];
#pragma unroll
    for (int j = 0; j < 4; j++) {
        float v = sb[j0 + j];
#pragma unroll
        for (int k = 0; k < INF_; k++) v += acc[k] * sW[k * HID + j0 + j];
        ov[j] = fmaxf(v, 0.0f);
    }
    __half2 p0 = __floats2half2_rn(ov[0], ov[1]);
    __half2 p1 = __floats2half2_rn(ov[2], ov[3]);
    uint2 pk;
    pk.x = *(uint32_t*)&p0;
    pk.y = *(uint32_t*)&p1;
    *(uint2*)&g_h1[(size_t)i * HID + j0] = pk;
}

// ---------------- 128-feature CSR gather-aggregate (fp16 in/out) -----------
__global__ __launch_bounds__(512) void k_agg128(int src_sel) {
    const __half* __restrict__ h = (src_sel == 0) ? g_h1 : g_h2;
    int wid = threadIdx.x >> 5, lane = threadIdx.x & 31;
    int i = blockIdx.x * 16 + wid;
    if (i >= NN) return;
    int start = g_rowstart[i], len = g_indeg[i];
    float d = g_dis[i];
    float sw = d * d;

    uint2 self = *(const uint2*)&h[(size_t)i * HID + lane * 4];
    float2 s0 = __half22float2(*(__half2*)&self.x);
    float2 s1 = __half22float2(*(__half2*)&self.y);
    float4 acc = make_float4(sw * s0.x, sw * s0.y, sw * s1.x, sw * s1.y);

    int end = start + len;
#pragma unroll 4
    for (int e = start; e < end; ++e) {
        int2 ed = g_csr[e];
        float w = __int_as_float(ed.y);
        uint2 raw = *(const uint2*)&h[(size_t)ed.x * HID + lane * 4];
        float2 v0 = __half22float2(*(__half2*)&raw.x);
        float2 v1 = __half22float2(*(__half2*)&raw.y);
        acc.x += w * v0.x; acc.y += w * v0.y; acc.z += w * v1.x; acc.w += w * v1.y;
    }
    __half2 p0 = __floats2half2_rn(acc.x, acc.y);
    __half2 p1 = __floats2half2_rn(acc.z, acc.w);
    uint2 pk;
    pk.x = *(uint32_t*)&p0;
    pk.y = *(uint32_t*)&p1;
    *(uint2*)&g_agg[(size_t)i * HID + lane * 4] = pk;
}

// ---------------- fp16 tensor-core GEMM: C = relu(g_agg @ W + b) -----------
__device__ __forceinline__ void mma_f16(float& d0, float& d1, float& d2, float& d3,
                                        uint32_t a0, uint32_t a1, uint32_t a2, uint32_t a3,
                                        uint32_t b0, uint32_t b1) {
    asm volatile(
        "mma.sync.aligned.m16n8k16.row.col.f32.f16.f16.f32 "
        "{%0,%1,%2,%3}, {%4,%5,%6,%7}, {%8,%9}, {%0,%1,%2,%3};"
        : "+f"(d0), "+f"(d1), "+f"(d2), "+f"(d3)
        : "r"(a0), "r"(a1), "r"(a2), "r"(a3), "r"(b0), "r"(b1));
}

__global__ __launch_bounds__(256, 2) void k_gemm_tc(int out_sel,
                                                    const float* __restrict__ W,
                                                    const float* __restrict__ b) {
    __half* __restrict__ C = (out_sel == 0) ? g_h2 : g_h1;
    const __half* __restrict__ A = g_agg;
    __shared__ uint2 sB[16][8][32];  // [n_frag][k_step][lane] = {b0, b1}
    __shared__ float sb[HID];

    int tid = threadIdx.x;
    int wid = tid >> 5, lane = tid & 31;
    int grp = lane >> 2, t4 = lane & 3;
    if (tid < HID) sb[tid] = b[tid];

    for (int idx = tid; idx < 16 * 8 * 32; idx += 256) {
        int l = idx & 31;
        int ks = (idx >> 5) & 7;
        int nf = idx >> 8;
        int kk = ks * 16 + 2 * (l & 3);
        int nn = nf * 8 + (l >> 2);
        __half2 v0 = __floats2half2_rn(W[kk * HID + nn], W[(kk + 1) * HID + nn]);
        __half2 v1 = __floats2half2_rn(W[(kk + 8) * HID + nn], W[(kk + 9) * HID + nn]);
        sB[nf][ks][l] = make_uint2(*(uint32_t*)&v0, *(uint32_t*)&v1);
    }

    int rbase = blockIdx.x * 128 + wid * 16;
    int r0 = rbase + grp;
    int r1 = rbase + grp + 8;
    int r0c = (r0 < NN) ? r0 : (NN - 1);
    int r1c = (r1 < NN) ? r1 : (NN - 1);

    uint32_t areg[8][4];
    int c0 = 2 * t4;
#pragma unroll
    for (int ks = 0; ks < 8; ks++) {
        int k0 = ks * 16;
        areg[ks][0] = *(const uint32_t*)&A[(size_t)r0c * HID + k0 + c0];
        areg[ks][1] = *(const uint32_t*)&A[(size_t)r1c * HID + k0 + c0];
        areg[ks][2] = *(const uint32_t*)&A[(size_t)r0c * HID + k0 + c0 + 8];
        areg[ks][3] = *(const uint32_t*)&A[(size_t)r1c * HID + k0 + c0 + 8];
    }
    __syncthreads();

    float cacc[16][4];
#pragma unroll
    for (int nf = 0; nf < 16; nf++)
#pragma unroll
        for (int q = 0; q < 4; q++) cacc[nf][q] = 0.0f;

#pragma unroll
    for (int ks = 0; ks < 8; ks++) {
#pragma unroll
        for (int nf = 0; nf < 16; nf++) {
            uint2 bv = sB[nf][ks][lane];
            mma_f16(cacc[nf][0], cacc[nf][1], cacc[nf][2], cacc[nf][3],
                    areg[ks][0], areg[ks][1], areg[ks][2], areg[ks][3],
                    bv.x, bv.y);
        }
    }

#pragma unroll
    for (int nf = 0; nf < 16; nf++) {
        int col = nf * 8 + 2 * t4;
        float bb0 = sb[col], bb1 = sb[col + 1];
        if (r0 < NN) {
            __half2 o = __floats2half2_rn(fmaxf(cacc[nf][0] + bb0, 0.0f),
                                          fmaxf(cacc[nf][1] + bb1, 0.0f));
            *(__half2*)&C[(size_t)r0 * HID + col] = o;
        }
        if (r1 < NN) {
            __half2 o = __floats2half2_rn(fmaxf(cacc[nf][2] + bb0, 0.0f),
                                          fmaxf(cacc[nf][3] + bb1, 0.0f));
            *(__half2*)&C[(size_t)r1 * HID + col] = o;
        }
    }
}

// ---------------- fused segment-max pool + linear head ----------------------
// One block per graph; batch is sorted so segment bounds come from binary search.
__global__ __launch_bounds__(128) void k_poolhead(const int* __restrict__ batch,
                                                  const float* __restrict__ Wl,
                                                  const float* __restrict__ bl,
                                                  float* __restrict__ out) {
    const __half* __restrict__ h = g_h1;  // final layer output lives in g_h1
    int g = blockIdx.x;
    int f = threadIdx.x;  // 0..127

    // lower_bound(batch, g) and lower_bound(batch, g+1), computed redundantly
    int lo = 0, hi = NN;
    while (lo < hi) { int mid = (lo + hi) >> 1; if (batch[mid] < g) lo = mid + 1; else hi = mid; }
    int start = lo;
    hi = NN;
    while (lo < hi) { int mid = (lo + hi) >> 1; if (batch[mid] < g + 1) lo = mid + 1; else hi = mid; }
    int end = lo;

    float m = 0.0f;  // post-relu values are >= 0
    for (int n = start; n < end; ++n)
        m = fmaxf(m, __half2float(h[(size_t)n * HID + f]));

    // head: out[g*2+c] = sum_f m_f * Wl[f*2+c] + bl[c]
    __shared__ float2 sp[128];
    sp[f] = make_float2(m * Wl[f * 2 + 0], m * Wl[f * 2 + 1]);
    __syncthreads();
#pragma unroll
    for (int off = 64; off >= 1; off >>= 1) {
        if (f < off) {
            sp[f].x += sp[f + off].x;
            sp[f].y += sp[f + off].y;
        }
        __syncthreads();
    }
    if (f == 0) {
        out[g * 2 + 0] = sp[0].x + bl[0];
        out[g * 2 + 1] = sp[0].y + bl[1];
    }
}

// ---------------- launch -----------------------------------------------------
extern "C" void kernel_launch(void* const* d_in, const int* in_sizes, int n_in,
                              void* d_out, int out_size) {
    const float* x   = (const float*)d_in[0];
    const int* ei    = (const int*)d_in[1];
    const int* batch = (const int*)d_in[2];
    const float* W1  = (const float*)d_in[3];
    const float* b1  = (const float*)d_in[4];
    const float* W2  = (const float*)d_in[5];
    const float* b2  = (const float*)d_in[6];
    const float* W3  = (const float*)d_in[7];
    const float* b3  = (const float*)d_in[8];
    const float* Wl  = (const float*)d_in[9];
    const float* bl  = (const float*)d_in[10];
    float* out = (float*)d_out;

    const int* src = ei;
    const int* dst = ei + NE;

    // CSR build (counting sort by dst) + degree normalization
    k_init<<<(NN + 255) / 256, 256>>>();
    k_hist<<<(NE + 255) / 256, 256>>>(dst);
    k_scan1<<<SCAN_BLK, 1024>>>();   // scan + lookback + g_dis
    k_scatter<<<(NE + 255) / 256, 256>>>(src, dst);

    // Layer 1: aggregate raw x (7 feats) then fused 7x128 GEMM + bias + relu
    k_layer1<<<(NN + 7) / 8, 256>>>(x, W1, b1);        // -> g_h1 (fp16)

    // Layer 2
    k_agg128<<<(NN + 15) / 16, 512>>>(0);              // g_h1 -> g_agg (fp16)
    k_gemm_tc<<<(NN + 127) / 128, 256>>>(0, W2, b2);   // g_agg -> g_h2 (fp16)

    // Layer 3
    k_agg128<<<(NN + 15) / 16, 512>>>(1);              // g_h2 -> g_agg
    k_gemm_tc<<<(NN + 127) / 128, 256>>>(1, W3, b3);   // g_agg -> g_h1

    // Fused pool + head
    k_poolhead<<<NG, 128>>>(batch, Wl, bl, out);
}

// round 13
// speedup vs baseline: 1.7292x; 1.0561x over previous
#include <cuda_runtime.h>
#include <cuda_fp16.h>
#include <cstdint>

#define NN 100000
#define NE 1600000
#define HID 128
#define INF_ 7
#define NG 512
#define SCAN_BLK ((NN + 1023) / 1024)

// ---------------- scratch (device globals: no allocation allowed) ----------
__device__ int    g_indeg[NN];
__device__ int    g_cursor[NN];      // seeded to rowstart by k_scan1; atomicAdd slot source
__device__ int    g_rowstart[NN];    // GLOBAL exclusive scan (lookback in k_scan1)
__device__ float  g_dis[NN];
__device__ int2   g_csr[NE];         // {src, __float_as_int(weight)}
__device__ int    g_aggpub[SCAN_BLK];// lookback: block aggregate + 1 (0 = not ready)
__device__ __half g_x16[(size_t)NN * 8];    // x packed to fp16, 8 halfs/row (pad 0)
__device__ __half g_h1[(size_t)NN * HID];   // hidden features fp16 (gather operand)
__device__ __half g_h2[(size_t)NN * HID];
__device__ __half g_agg[(size_t)NN * HID];  // fp16 aggregated features (GEMM A)

// ---------------- graph preprocessing --------------------------------------
__global__ void k_init() {
    int i = blockIdx.x * blockDim.x + threadIdx.x;
    if (i < NN) g_indeg[i] = 0;
    if (i < SCAN_BLK) g_aggpub[i] = 0;
}

__global__ void k_hist(const int* __restrict__ dst) {
    int e = blockIdx.x * blockDim.x + threadIdx.x;
    if (e < NE) atomicAdd(&g_indeg[dst[e]], 1);
}

// pack x [NN,7] fp32 -> [NN,8] fp16 (16B rows, single-sector gathers)
__global__ void k_packx(const float* __restrict__ x) {
    int i = blockIdx.x * blockDim.x + threadIdx.x;
    if (i >= NN) return;
    const float* xr = x + (size_t)i * INF_;
    __half2 p0 = __floats2half2_rn(xr[0], xr[1]);
    __half2 p1 = __floats2half2_rn(xr[2], xr[3]);
    __half2 p2 = __floats2half2_rn(xr[4], xr[5]);
    __half2 p3 = __floats2half2_rn(xr[6], 0.0f);
    uint4 pk;
    pk.x = *(uint32_t*)&p0; pk.y = *(uint32_t*)&p1;
    pk.z = *(uint32_t*)&p2; pk.w = *(uint32_t*)&p3;
    *(uint4*)&g_x16[(size_t)i * 8] = pk;
}

// Single-pass scan: block-local scan + decoupled lookback over block aggregates.
// All SCAN_BLK=98 blocks are co-resident (98 <= 148 SMs), so polling is safe.
// Also seeds g_cursor = rowstart so k_scatter's atomicAdd yields the slot directly.
__global__ void k_scan1() {
    __shared__ int s[1024];
    __shared__ int s_off;
    int tid = threadIdx.x;
    int bid = blockIdx.x;
    int i = bid * 1024 + tid;
    int v = (i < NN) ? g_indeg[i] : 0;
    if (i < NN) g_dis[i] = rsqrtf((float)(v + 1));  // +1 self loop
    s[tid] = v;
    __syncthreads();
    for (int off = 1; off < 1024; off <<= 1) {
        int t = (tid >= off) ? s[tid - off] : 0;
        __syncthreads();
        s[tid] += t;
        __syncthreads();
    }
    // publish this block's aggregate (+1 so 0 means "not ready")
    if (tid == 1023) atomicExch(&g_aggpub[bid], s[1023] + 1);
    if (tid == 0) s_off = 0;
    __syncthreads();
    // lookback: thread t polls predecessor t's aggregate
    if (tid < bid) {
        volatile int* p = &g_aggpub[tid];
        int a;
        do { a = *p; } while (a == 0);
        atomicAdd(&s_off, a - 1);
    }
    __syncthreads();
    if (i < NN) {
        int rs = s_off + s[tid] - v;  // global exclusive scan
        g_rowstart[i] = rs;
        g_cursor[i] = rs;             // seed cursor with rowstart
    }
}

__global__ void k_scatter(const int* __restrict__ src, const int* __restrict__ dst) {
    int e = blockIdx.x * blockDim.x + threadIdx.x;
    if (e >= NE) return;
    int s = src[e], d = dst[e];
    int slot = atomicAdd(&g_cursor[d], 1);   // cursor pre-seeded to rowstart
    g_csr[slot] = make_int2(s, __float_as_int(g_dis[s] * g_dis[d]));
}

// ---------------- layer 1: aggregate x16 (8 halfs) fused with 7x128 GEMM ---
__global__ void k_layer1(const float* __restrict__ W1, const float* __restrict__ b1) {
    __shared__ float sW[INF_ * HID];
    __shared__ float sb[HID];
    int tid = threadIdx.x;
    for (int j = tid; j < INF_ * HID; j += blockDim.x) sW[j] = W1[j];
    if (tid < HID) sb[tid] = b1[tid];
    __syncthreads();

    int wid = tid >> 5, lane = tid & 31;
    int i = blockIdx.x * 8 + wid;
    if (i >= NN) return;

    int start = g_rowstart[i], len = g_indeg[i];
    float acc[8];
#pragma unroll
    for (int k = 0; k < 8; k++) acc[k] = 0.0f;

    for (int e = start + lane; e < start + len; e += 32) {
        int2 ed = g_csr[e];
        float w = __int_as_float(ed.y);
        uint4 raw = *(const uint4*)&g_x16[(size_t)ed.x * 8];
        float2 v0 = __half22float2(*(__half2*)&raw.x);
        float2 v1 = __half22float2(*(__half2*)&raw.y);
        float2 v2 = __half22float2(*(__half2*)&raw.z);
        float2 v3 = __half22float2(*(__half2*)&raw.w);
        acc[0] += w * v0.x; acc[1] += w * v0.y;
        acc[2] += w * v1.x; acc[3] += w * v1.y;
        acc[4] += w * v2.x; acc[5] += w * v2.y;
        acc[6] += w * v3.x; acc[7] += w * v3.y;
    }
#pragma unroll
    for (int k = 0; k < INF_; k++) {
#pragma unroll
        for (int off = 16; off > 0; off >>= 1)
            acc[k] += __shfl_xor_sync(0xffffffffu, acc[k], off);
    }
    float d = g_dis[i];
    float sw = d * d;
    {
        uint4 raw = *(const uint4*)&g_x16[(size_t)i * 8];
        float2 v0 = __half22float2(*(__half2*)&raw.x);
        float2 v1 = __half22float2(*(__half2*)&raw.y);
        float2 v2 = __half22float2(*(__half2*)&raw.z);
        float2 v3 = __half22float2(*(__half2*)&raw.w);
        acc[0] += sw * v0.x; acc[1] += sw * v0.y;
        acc[2] += sw * v1.x; acc[3] += sw * v1.y;
        acc[4] += sw * v2.x; acc[5] += sw * v2.y;
        acc[6] += sw * v3.x;
    }

    int j0 = lane * 4;
    float ov[4];
#pragma unroll
    for (int j = 0; j < 4; j++) {
        float v = sb[j0 + j];
#pragma unroll
        for (int k = 0; k < INF_; k++) v += acc[k] * sW[k * HID + j0 + j];
        ov[j] = fmaxf(v, 0.0f);
    }
    __half2 p0 = __floats2half2_rn(ov[0], ov[1]);
    __half2 p1 = __floats2half2_rn(ov[2], ov[3]);
    uint2 pk;
    pk.x = *(uint32_t*)&p0;
    pk.y = *(uint32_t*)&p1;
    *(uint2*)&g_h1[(size_t)i * HID + j0] = pk;
}

// ---------------- 128-feature CSR gather-aggregate (fp16 in/out) -----------
__global__ __launch_bounds__(512) void k_agg128(int src_sel) {
    const __half* __restrict__ h = (src_sel == 0) ? g_h1 : g_h2;
    int wid = threadIdx.x >> 5, lane = threadIdx.x & 31;
    int i = blockIdx.x * 16 + wid;
    if (i >= NN) return;
    int start = g_rowstart[i], len = g_indeg[i];
    float d = g_dis[i];
    float sw = d * d;

    uint2 self = *(const uint2*)&h[(size_t)i * HID + lane * 4];
    float2 s0 = __half22float2(*(__half2*)&self.x);
    float2 s1 = __half22float2(*(__half2*)&self.y);
    float4 acc = make_float4(sw * s0.x, sw * s0.y, sw * s1.x, sw * s1.y);

    int end = start + len;
#pragma unroll 4
    for (int e = start; e < end; ++e) {
        int2 ed = g_csr[e];
        float w = __int_as_float(ed.y);
        uint2 raw = *(const uint2*)&h[(size_t)ed.x * HID + lane * 4];
        float2 v0 = __half22float2(*(__half2*)&raw.x);
        float2 v1 = __half22float2(*(__half2*)&raw.y);
        acc.x += w * v0.x; acc.y += w * v0.y; acc.z += w * v1.x; acc.w += w * v1.y;
    }
    __half2 p0 = __floats2half2_rn(acc.x, acc.y);
    __half2 p1 = __floats2half2_rn(acc.z, acc.w);
    uint2 pk;
    pk.x = *(uint32_t*)&p0;
    pk.y = *(uint32_t*)&p1;
    *(uint2*)&g_agg[(size_t)i * HID + lane * 4] = pk;
}

// ---------------- fp16 tensor-core GEMM: C = relu(g_agg @ W + b) -----------
__device__ __forceinline__ void mma_f16(float& d0, float& d1, float& d2, float& d3,
                                        uint32_t a0, uint32_t a1, uint32_t a2, uint32_t a3,
                                        uint32_t b0, uint32_t b1) {
    asm volatile(
        "mma.sync.aligned.m16n8k16.row.col.f32.f16.f16.f32 "
        "{%0,%1,%2,%3}, {%4,%5,%6,%7}, {%8,%9}, {%0,%1,%2,%3};"
        : "+f"(d0), "+f"(d1), "+f"(d2), "+f"(d3)
        : "r"(a0), "r"(a1), "r"(a2), "r"(a3), "r"(b0), "r"(b1));
}

__global__ __launch_bounds__(256, 2) void k_gemm_tc(int out_sel,
                                                    const float* __restrict__ W,
                                                    const float* __restrict__ b) {
    __half* __restrict__ C = (out_sel == 0) ? g_h2 : g_h1;
    const __half* __restrict__ A = g_agg;
    __shared__ uint2 sB[16][8][32];  // [n_frag][k_step][lane] = {b0, b1}
    __shared__ float sb[HID];

    int tid = threadIdx.x;
    int wid = tid >> 5, lane = tid & 31;
    int grp = lane >> 2, t4 = lane & 3;
    if (tid < HID) sb[tid] = b[tid];

    for (int idx = tid; idx < 16 * 8 * 32; idx += 256) {
        int l = idx & 31;
        int ks = (idx >> 5) & 7;
        int nf = idx >> 8;
        int kk = ks * 16 + 2 * (l & 3);
        int nn = nf * 8 + (l >> 2);
        __half2 v0 = __floats2half2_rn(W[kk * HID + nn], W[(kk + 1) * HID + nn]);
        __half2 v1 = __floats2half2_rn(W[(kk + 8) * HID + nn], W[(kk + 9) * HID + nn]);
        sB[nf][ks][l] = make_uint2(*(uint32_t*)&v0, *(uint32_t*)&v1);
    }

    int rbase = blockIdx.x * 128 + wid * 16;
    int r0 = rbase + grp;
    int r1 = rbase + grp + 8;
    int r0c = (r0 < NN) ? r0 : (NN - 1);
    int r1c = (r1 < NN) ? r1 : (NN - 1);

    uint32_t areg[8][4];
    int c0 = 2 * t4;
#pragma unroll
    for (int ks = 0; ks < 8; ks++) {
        int k0 = ks * 16;
        areg[ks][0] = *(const uint32_t*)&A[(size_t)r0c * HID + k0 + c0];
        areg[ks][1] = *(const uint32_t*)&A[(size_t)r1c * HID + k0 + c0];
        areg[ks][2] = *(const uint32_t*)&A[(size_t)r0c * HID + k0 + c0 + 8];
        areg[ks][3] = *(const uint32_t*)&A[(size_t)r1c * HID + k0 + c0 + 8];
    }
    __syncthreads();

    float cacc[16][4];
#pragma unroll
    for (int nf = 0; nf < 16; nf++)
#pragma unroll
        for (int q = 0; q < 4; q++) cacc[nf][q] = 0.0f;

#pragma unroll
    for (int ks = 0; ks < 8; ks++) {
#pragma unroll
        for (int nf = 0; nf < 16; nf++) {
            uint2 bv = sB[nf][ks][lane];
            mma_f16(cacc[nf][0], cacc[nf][1], cacc[nf][2], cacc[nf][3],
                    areg[ks][0], areg[ks][1], areg[ks][2], areg[ks][3],
                    bv.x, bv.y);
        }
    }

#pragma unroll
    for (int nf = 0; nf < 16; nf++) {
        int col = nf * 8 + 2 * t4;
        float bb0 = sb[col], bb1 = sb[col + 1];
        if (r0 < NN) {
            __half2 o = __floats2half2_rn(fmaxf(cacc[nf][0] + bb0, 0.0f),
                                          fmaxf(cacc[nf][1] + bb1, 0.0f));
            *(__half2*)&C[(size_t)r0 * HID + col] = o;
        }
        if (r1 < NN) {
            __half2 o = __floats2half2_rn(fmaxf(cacc[nf][2] + bb0, 0.0f),
                                          fmaxf(cacc[nf][3] + bb1, 0.0f));
            *(__half2*)&C[(size_t)r1 * HID + col] = o;
        }
    }
}

// ---------------- fused segment-max pool + linear head ----------------------
// One block per graph; batch is sorted so segment bounds come from binary search.
__global__ __launch_bounds__(128) void k_poolhead(const int* __restrict__ batch,
                                                  const float* __restrict__ Wl,
                                                  const float* __restrict__ bl,
                                                  float* __restrict__ out) {
    const __half* __restrict__ h = g_h1;  // final layer output lives in g_h1
    int g = blockIdx.x;
    int f = threadIdx.x;  // 0..127

    // lower_bound(batch, g) and lower_bound(batch, g+1)
    int lo = 0, hi = NN;
    while (lo < hi) { int mid = (lo + hi) >> 1; if (batch[mid] < g) lo = mid + 1; else hi = mid; }
    int start = lo;
    hi = NN;
    while (lo < hi) { int mid = (lo + hi) >> 1; if (batch[mid] < g + 1) lo = mid + 1; else hi = mid; }
    int end = lo;

    float m = 0.0f;  // post-relu values are >= 0
    for (int n = start; n < end; ++n)
        m = fmaxf(m, __half2float(h[(size_t)n * HID + f]));

    // head: out[g*2+c] = sum_f m_f * Wl[f*2+c] + bl[c]
    __shared__ float2 sp[128];
    sp[f] = make_float2(m * Wl[f * 2 + 0], m * Wl[f * 2 + 1]);
    __syncthreads();
#pragma unroll
    for (int off = 64; off >= 1; off >>= 1) {
        if (f < off) {
            sp[f].x += sp[f + off].x;
            sp[f].y += sp[f + off].y;
        }
        __syncthreads();
    }
    if (f == 0) {
        out[g * 2 + 0] = sp[0].x + bl[0];
        out[g * 2 + 1] = sp[0].y + bl[1];
    }
}

// ---------------- launch -----------------------------------------------------
extern "C" void kernel_launch(void* const* d_in, const int* in_sizes, int n_in,
                              void* d_out, int out_size) {
    const float* x   = (const float*)d_in[0];
    const int* ei    = (const int*)d_in[1];
    const int* batch = (const int*)d_in[2];
    const float* W1  = (const float*)d_in[3];
    const float* b1  = (const float*)d_in[4];
    const float* W2  = (const float*)d_in[5];
    const float* b2  = (const float*)d_in[6];
    const float* W3  = (const float*)d_in[7];
    const float* b3  = (const float*)d_in[8];
    const float* Wl  = (const float*)d_in[9];
    const float* bl  = (const float*)d_in[10];
    float* out = (float*)d_out;

    const int* src = ei;
    const int* dst = ei + NE;

    // CSR build (counting sort by dst) + degree normalization
    k_init<<<(NN + 255) / 256, 256>>>();
    k_hist<<<(NE + 255) / 256, 256>>>(dst);
    k_packx<<<(NN + 255) / 256, 256>>>(x);
    k_scan1<<<SCAN_BLK, 1024>>>();   // scan + lookback + g_dis + cursor seed
    k_scatter<<<(NE + 255) / 256, 256>>>(src, dst);

    // Layer 1: aggregate packed x (8 halfs) then fused 7x128 GEMM + bias + relu
    k_layer1<<<(NN + 7) / 8, 256>>>(W1, b1);           // -> g_h1 (fp16)

    // Layer 2
    k_agg128<<<(NN + 15) / 16, 512>>>(0);              // g_h1 -> g_agg (fp16)
    k_gemm_tc<<<(NN + 127) / 128, 256>>>(0, W2, b2);   // g_agg -> g_h2 (fp16)

    // Layer 3
    k_agg128<<<(NN + 15) / 16, 512>>>(1);              // g_h2 -> g_agg
    k_gemm_tc<<<(NN + 127) / 128, 256>>>(1, W3, b3);   // g_agg -> g_h1

    // Fused pool + head
    k_poolhead<<<NG, 128>>>(batch, Wl, bl, out);
}

// round 17
// speedup vs baseline: 1.8699x; 1.0814x over previous
#include <cuda_runtime.h>
#include <cuda_fp16.h>
#include <cstdint>

#define NN 100000
#define NE 1600000
#define HID 128
#define INF_ 7
#define NG 512
#define SCAN_BLK ((NN + 1023) / 1024)

// ---------------- scratch (device globals: no allocation allowed) ----------
__device__ int    g_indeg[NN];
__device__ int    g_cursor[NN];      // seeded to rowstart by k_scan1
__device__ int    g_rowstart[NN];    // GLOBAL exclusive scan (lookback in k_scan1)
__device__ float  g_dis[NN];
__device__ int    g_csr[NE];         // src only — weights folded into node scaling!
__device__ int    g_aggpub[SCAN_BLK];
__device__ __half g_x16[(size_t)NN * 8];    // dis_i * x[i] packed fp16 (pad 0)
__device__ __half g_h1[(size_t)NN * HID];   // pre-scaled features dis*h (layers 1,2)
__device__ __half g_h2[(size_t)NN * HID];
__device__ __half g_agg[(size_t)NN * HID];  // fp16 aggregated features (GEMM A)

// ---------------- graph preprocessing --------------------------------------
__global__ void k_init() {
    int i = blockIdx.x * blockDim.x + threadIdx.x;
    if (i < NN) g_indeg[i] = 0;
    if (i < SCAN_BLK) g_aggpub[i] = 0;
}

__global__ void k_hist(const int* __restrict__ dst) {
    int e = blockIdx.x * blockDim.x + threadIdx.x;
    if (e < NE) atomicAdd(&g_indeg[dst[e]], 1);
}

// Single-pass scan + lookback; computes dis, seeds cursor=rowstart.
__global__ void k_scan1() {
    __shared__ int s[1024];
    __shared__ int s_off;
    int tid = threadIdx.x;
    int bid = blockIdx.x;
    int i = bid * 1024 + tid;
    int v = (i < NN) ? g_indeg[i] : 0;
    if (i < NN) g_dis[i] = rsqrtf((float)(v + 1));  // +1 self loop
    s[tid] = v;
    __syncthreads();
    for (int off = 1; off < 1024; off <<= 1) {
        int t = (tid >= off) ? s[tid - off] : 0;
        __syncthreads();
        s[tid] += t;
        __syncthreads();
    }
    if (tid == 1023) atomicExch(&g_aggpub[bid], s[1023] + 1);
    if (tid == 0) s_off = 0;
    __syncthreads();
    if (tid < bid) {
        volatile int* p = &g_aggpub[tid];
        int a;
        do { a = *p; } while (a == 0);
        atomicAdd(&s_off, a - 1);
    }
    __syncthreads();
    if (i < NN) {
        int rs = s_off + s[tid] - v;
        g_rowstart[i] = rs;
        g_cursor[i] = rs;
    }
}

// scatter (src only, no weight) + pack dis*x into fp16 rows (same launch)
__global__ void k_scatter(const int* __restrict__ src, const int* __restrict__ dst,
                          const float* __restrict__ x) {
    int e = blockIdx.x * blockDim.x + threadIdx.x;
    if (e < NE) {
        int d = dst[e];
        int slot = atomicAdd(&g_cursor[d], 1);
        g_csr[slot] = src[e];
    }
    if (e < NN) {
        float di = g_dis[e];
        const float* xr = x + (size_t)e * INF_;
        __half2 p0 = __floats2half2_rn(di * xr[0], di * xr[1]);
        __half2 p1 = __floats2half2_rn(di * xr[2], di * xr[3]);
        __half2 p2 = __floats2half2_rn(di * xr[4], di * xr[5]);
        __half2 p3 = __floats2half2_rn(di * xr[6], 0.0f);
        uint4 pk;
        pk.x = *(uint32_t*)&p0; pk.y = *(uint32_t*)&p1;
        pk.z = *(uint32_t*)&p2; pk.w = *(uint32_t*)&p3;
        *(uint4*)&g_x16[(size_t)e * 8] = pk;
    }
}

// ---------------- layer 1: aggregate x̂ (8 halfs) + fused 7x128 GEMM --------
// x̂ = dis*x, so agg_i = dis_i * (Σ_s x̂[s] + x̂[i]); output stored as dis_i*relu.
__global__ void k_layer1(const float* __restrict__ W1, const float* __restrict__ b1) {
    __shared__ float sW[INF_ * HID];
    __shared__ float sb[HID];
    int tid = threadIdx.x;
    for (int j = tid; j < INF_ * HID; j += blockDim.x) sW[j] = W1[j];
    if (tid < HID) sb[tid] = b1[tid];
    __syncthreads();

    int wid = tid >> 5, lane = tid & 31;
    int i = blockIdx.x * 8 + wid;
    if (i >= NN) return;

    int start = g_rowstart[i], len = g_indeg[i];
    float acc[8];
#pragma unroll
    for (int k = 0; k < 8; k++) acc[k] = 0.0f;

    for (int e = start + lane; e < start + len; e += 32) {
        int s = g_csr[e];
        uint4 raw = *(const uint4*)&g_x16[(size_t)s * 8];
        float2 v0 = __half22float2(*(__half2*)&raw.x);
        float2 v1 = __half22float2(*(__half2*)&raw.y);
        float2 v2 = __half22float2(*(__half2*)&raw.z);
        float2 v3 = __half22float2(*(__half2*)&raw.w);
        acc[0] += v0.x; acc[1] += v0.y;
        acc[2] += v1.x; acc[3] += v1.y;
        acc[4] += v2.x; acc[5] += v2.y;
        acc[6] += v3.x; acc[7] += v3.y;
    }
#pragma unroll
    for (int k = 0; k < INF_; k++) {
#pragma unroll
        for (int off = 16; off > 0; off >>= 1)
            acc[k] += __shfl_xor_sync(0xffffffffu, acc[k], off);
    }
    float di = g_dis[i];
    {   // self term x̂[i], then complete normalization: *dis_i
        uint4 raw = *(const uint4*)&g_x16[(size_t)i * 8];
        float2 v0 = __half22float2(*(__half2*)&raw.x);
        float2 v1 = __half22float2(*(__half2*)&raw.y);
        float2 v2 = __half22float2(*(__half2*)&raw.z);
        float2 v3 = __half22float2(*(__half2*)&raw.w);
        acc[0] = di * (acc[0] + v0.x); acc[1] = di * (acc[1] + v0.y);
        acc[2] = di * (acc[2] + v1.x); acc[3] = di * (acc[3] + v1.y);
        acc[4] = di * (acc[4] + v2.x); acc[5] = di * (acc[5] + v2.y);
        acc[6] = di * (acc[6] + v3.x);
    }

    int j0 = lane * 4;
    float ov[4];
#pragma unroll
    for (int j = 0; j < 4; j++) {
        float v = sb[j0 + j];
#pragma unroll
        for (int k = 0; k < INF_; k++) v += acc[k] * sW[k * HID + j0 + j];
        ov[j] = di * fmaxf(v, 0.0f);   // pre-scale output for next aggregation
    }
    __half2 p0 = __floats2half2_rn(ov[0], ov[1]);
    __half2 p1 = __floats2half2_rn(ov[2], ov[3]);
    uint2 pk;
    pk.x = *(uint32_t*)&p0;
    pk.y = *(uint32_t*)&p1;
    *(uint2*)&g_h1[(size_t)i * HID + j0] = pk;
}

// ---------------- 128-feature CSR gather-aggregate (weightless) ------------
// h holds ĥ = dis*h; agg_i = dis_i * (Σ_s ĥ[s] + ĥ[i]).
__global__ __launch_bounds__(512) void k_agg128(int src_sel) {
    const __half* __restrict__ h = (src_sel == 0) ? g_h1 : g_h2;
    int wid = threadIdx.x >> 5, lane = threadIdx.x & 31;
    int i = blockIdx.x * 16 + wid;
    if (i >= NN) return;
    int start = g_rowstart[i], len = g_indeg[i];

    uint2 self = *(const uint2*)&h[(size_t)i * HID + lane * 4];
    float2 s0 = __half22float2(*(__half2*)&self.x);
    float2 s1 = __half22float2(*(__half2*)&self.y);
    float4 acc = make_float4(s0.x, s0.y, s1.x, s1.y);

    int end = start + len;
#pragma unroll 4
    for (int e = start; e < end; ++e) {
        int s = g_csr[e];
        uint2 raw = *(const uint2*)&h[(size_t)s * HID + lane * 4];
        float2 v0 = __half22float2(*(__half2*)&raw.x);
        float2 v1 = __half22float2(*(__half2*)&raw.y);
        acc.x += v0.x; acc.y += v0.y; acc.z += v1.x; acc.w += v1.y;
    }
    float di = g_dis[i];
    __half2 p0 = __floats2half2_rn(di * acc.x, di * acc.y);
    __half2 p1 = __floats2half2_rn(di * acc.z, di * acc.w);
    uint2 pk;
    pk.x = *(uint32_t*)&p0;
    pk.y = *(uint32_t*)&p1;
    *(uint2*)&g_agg[(size_t)i * HID + lane * 4] = pk;
}

// ---------------- fp16 tensor-core GEMM: C = relu(g_agg @ W + b) -----------
// scale_out=1: store dis*relu (feeds next aggregation). 0: store relu (final).
__device__ __forceinline__ void mma_f16(float& d0, float& d1, float& d2, float& d3,
                                        uint32_t a0, uint32_t a1, uint32_t a2, uint32_t a3,
                                        uint32_t b0, uint32_t b1) {
    asm volatile(
        "mma.sync.aligned.m16n8k16.row.col.f32.f16.f16.f32 "
        "{%0,%1,%2,%3}, {%4,%5,%6,%7}, {%8,%9}, {%0,%1,%2,%3};"
        : "+f"(d0), "+f"(d1), "+f"(d2), "+f"(d3)
        : "r"(a0), "r"(a1), "r"(a2), "r"(a3), "r"(b0), "r"(b1));
}

__global__ __launch_bounds__(256, 2) void k_gemm_tc(int out_sel, int scale_out,
                                                    const float* __restrict__ W,
                                                    const float* __restrict__ b) {
    __half* __restrict__ C = (out_sel == 0) ? g_h2 : g_h1;
    const __half* __restrict__ A = g_agg;
    __shared__ uint2 sB[16][8][32];  // [n_frag][k_step][lane] = {b0, b1}
    __shared__ float sb[HID];

    int tid = threadIdx.x;
    int wid = tid >> 5, lane = tid & 31;
    int grp = lane >> 2, t4 = lane & 3;
    if (tid < HID) sb[tid] = b[tid];

    for (int idx = tid; idx < 16 * 8 * 32; idx += 256) {
        int l = idx & 31;
        int ks = (idx >> 5) & 7;
        int nf = idx >> 8;
        int kk = ks * 16 + 2 * (l & 3);
        int nn = nf * 8 + (l >> 2);
        __half2 v0 = __floats2half2_rn(W[kk * HID + nn], W[(kk + 1) * HID + nn]);
        __half2 v1 = __floats2half2_rn(W[(kk + 8) * HID + nn], W[(kk + 9) * HID + nn]);
        sB[nf][ks][l] = make_uint2(*(uint32_t*)&v0, *(uint32_t*)&v1);
    }

    int rbase = blockIdx.x * 128 + wid * 16;
    int r0 = rbase + grp;
    int r1 = rbase + grp + 8;
    int r0c = (r0 < NN) ? r0 : (NN - 1);
    int r1c = (r1 < NN) ? r1 : (NN - 1);

    uint32_t areg[8][4];
    int c0 = 2 * t4;
#pragma unroll
    for (int ks = 0; ks < 8; ks++) {
        int k0 = ks * 16;
        areg[ks][0] = *(const uint32_t*)&A[(size_t)r0c * HID + k0 + c0];
        areg[ks][1] = *(const uint32_t*)&A[(size_t)r1c * HID + k0 + c0];
        areg[ks][2] = *(const uint32_t*)&A[(size_t)r0c * HID + k0 + c0 + 8];
        areg[ks][3] = *(const uint32_t*)&A[(size_t)r1c * HID + k0 + c0 + 8];
    }
    float sc0 = scale_out ? g_dis[r0c] : 1.0f;
    float sc1 = scale_out ? g_dis[r1c] : 1.0f;
    __syncthreads();

    float cacc[16][4];
#pragma unroll
    for (int nf = 0; nf < 16; nf++)
#pragma unroll
        for (int q = 0; q < 4; q++) cacc[nf][q] = 0.0f;

#pragma unroll
    for (int ks = 0; ks < 8; ks++) {
#pragma unroll
        for (int nf = 0; nf < 16; nf++) {
            uint2 bv = sB[nf][ks][lane];
            mma_f16(cacc[nf][0], cacc[nf][1], cacc[nf][2], cacc[nf][3],
                    areg[ks][0], areg[ks][1], areg[ks][2], areg[ks][3],
                    bv.x, bv.y);
        }
    }

#pragma unroll
    for (int nf = 0; nf < 16; nf++) {
        int col = nf * 8 + 2 * t4;
        float bb0 = sb[col], bb1 = sb[col + 1];
        if (r0 < NN) {
            __half2 o = __floats2half2_rn(sc0 * fmaxf(cacc[nf][0] + bb0, 0.0f),
                                          sc0 * fmaxf(cacc[nf][1] + bb1, 0.0f));
            *(__half2*)&C[(size_t)r0 * HID + col] = o;
        }
        if (r1 < NN) {
            __half2 o = __floats2half2_rn(sc1 * fmaxf(cacc[nf][2] + bb0, 0.0f),
                                          sc1 * fmaxf(cacc[nf][3] + bb1, 0.0f));
            *(__half2*)&C[(size_t)r1 * HID + col] = o;
        }
    }
}

// ---------------- fused segment-max pool + linear head ----------------------
__global__ __launch_bounds__(128) void k_poolhead(const int* __restrict__ batch,
                                                  const float* __restrict__ Wl,
                                                  const float* __restrict__ bl,
                                                  float* __restrict__ out) {
    const __half* __restrict__ h = g_h1;  // final (unscaled) layer output
    int g = blockIdx.x;
    int f = threadIdx.x;  // 0..127

    int lo = 0, hi = NN;
    while (lo < hi) { int mid = (lo + hi) >> 1; if (batch[mid] < g) lo = mid + 1; else hi = mid; }
    int start = lo;
    hi = NN;
    while (lo < hi) { int mid = (lo + hi) >> 1; if (batch[mid] < g + 1) lo = mid + 1; else hi = mid; }
    int end = lo;

    float m = 0.0f;  // post-relu values are >= 0
    for (int n = start; n < end; ++n)
        m = fmaxf(m, __half2float(h[(size_t)n * HID + f]));

    __shared__ float2 sp[128];
    sp[f] = make_float2(m * Wl[f * 2 + 0], m * Wl[f * 2 + 1]);
    __syncthreads();
#pragma unroll
    for (int off = 64; off >= 1; off >>= 1) {
        if (f < off) {
            sp[f].x += sp[f + off].x;
            sp[f].y += sp[f + off].y;
        }
        __syncthreads();
    }
    if (f == 0) {
        out[g * 2 + 0] = sp[0].x + bl[0];
        out[g * 2 + 1] = sp[0].y + bl[1];
    }
}

// ---------------- launch -----------------------------------------------------
extern "C" void kernel_launch(void* const* d_in, const int* in_sizes, int n_in,
                              void* d_out, int out_size) {
    const float* x   = (const float*)d_in[0];
    const int* ei    = (const int*)d_in[1];
    const int* batch = (const int*)d_in[2];
    const float* W1  = (const float*)d_in[3];
    const float* b1  = (const float*)d_in[4];
    const float* W2  = (const float*)d_in[5];
    const float* b2  = (const float*)d_in[6];
    const float* W3  = (const float*)d_in[7];
    const float* b3  = (const float*)d_in[8];
    const float* Wl  = (const float*)d_in[9];
    const float* bl  = (const float*)d_in[10];
    float* out = (float*)d_out;

    const int* src = ei;
    const int* dst = ei + NE;

    // CSR build (counting sort by dst, weightless) + degree normalization
    k_init<<<(NN + 255) / 256, 256>>>();
    k_hist<<<(NE + 255) / 256, 256>>>(dst);
    k_scan1<<<SCAN_BLK, 1024>>>();                       // scan + dis + cursor seed
    k_scatter<<<(NE + 255) / 256, 256>>>(src, dst, x);   // + pack dis*x -> fp16

    // Layer 1
    k_layer1<<<(NN + 7) / 8, 256>>>(W1, b1);             // -> g_h1 = dis*relu (fp16)

    // Layer 2
    k_agg128<<<(NN + 15) / 16, 512>>>(0);                // g_h1 -> g_agg
    k_gemm_tc<<<(NN + 127) / 128, 256>>>(0, 1, W2, b2);  // g_agg -> g_h2 = dis*relu

    // Layer 3
    k_agg128<<<(NN + 15) / 16, 512>>>(1);                // g_h2 -> g_agg
    k_gemm_tc<<<(NN + 127) / 128, 256>>>(1, 0, W3, b3);  // g_agg -> g_h1 = relu

    // Fused pool + head
    k_poolhead<<<NG, 128>>>(batch, Wl, bl, out);
}